// round 5
// baseline (speedup 1.0000x reference)
#include <cuda_runtime.h>
#include <cstdint>

// Problem constants
#define NTOK   8192      // B*S = 4*2048
#define DDIM   512
#define NEXP   16
#define HDIM   1024
#define CAP    8192

// ---------------- scratch (device globals: allocation-free) ----------------
__device__ float g_xn[NTOK * DDIM];             // normalized x (active rows only)
__device__ float g_hbuf[(2 * NTOK) * HDIM];     // silu(h) per assignment (row = 2t+k)
__device__ float g_contrib[(2 * NTOK) * DDIM];  // p*(h@w2+b2) per assignment
__device__ float g_rp[NTOK * NEXP];             // full gating prob rows (aux)
__device__ int   g_tok [NEXP * CAP];
__device__ float g_prob[NEXP * CAP];
__device__ int   g_pair[NEXP * CAP];            // 2t+k
__device__ int   g_keep[NTOK];
__device__ float g_z[NEXP * DDIM];              // expert output for zero input
__device__ int   g_cnt[NEXP];
__device__ int   g_bflag;

// ---------------- JAX threefry2x32, PARTITIONABLE path --------------------
__device__ __forceinline__ uint32_t rotl32(uint32_t x, int r) {
    return (x << r) | (x >> (32 - r));
}

__device__ __forceinline__ void threefry2x32(uint32_t k0, uint32_t k1,
                                             uint32_t& x0, uint32_t& x1) {
    uint32_t k2 = k0 ^ k1 ^ 0x1BD11BDAu;
#define TF_RND(r) { x0 += x1; x1 = rotl32(x1, r); x1 ^= x0; }
    x0 += k0; x1 += k1;
    TF_RND(13) TF_RND(15) TF_RND(26) TF_RND(6)
    x0 += k1; x1 += k2 + 1u;
    TF_RND(17) TF_RND(29) TF_RND(16) TF_RND(24)
    x0 += k2; x1 += k0 + 2u;
    TF_RND(13) TF_RND(15) TF_RND(26) TF_RND(6)
    x0 += k0; x1 += k1 + 3u;
    TF_RND(17) TF_RND(29) TF_RND(16) TF_RND(24)
    x0 += k1; x1 += k2 + 4u;
    TF_RND(13) TF_RND(15) TF_RND(26) TF_RND(6)
    x0 += k2; x1 += k0 + 5u;
#undef TF_RND
}

// noise[j], j in [0, NTOK*NEXP): jax.random.normal(key(42), (B,S,E)) * 0.01
// jax_threefry_partitionable=True (modern JAX default):
//   counts = iota(uint64); per element: threefry2x32(key, (hi32, lo32)),
//   32-bit output = out0 ^ out1.
__device__ __forceinline__ float jax_noise(uint32_t j) {
    uint32_t x0 = 0u, x1 = j;            // hi32(j)=0 for j < 2^32
    threefry2x32(0u, 42u, x0, x1);       // key(42) -> (0, 42)
    uint32_t bits = x0 ^ x1;
    uint32_t fb = (bits >> 9) | 0x3F800000u;
    float u01 = __uint_as_float(fb) - 1.0f;
    const float minval = __uint_as_float(0xBF7FFFFFu);  // nextafter(-1,0)
    float u = fmaf(u01, 2.0f, minval);                  // (hi-lo) rounds to 2.0f
    u = fmaxf(minval, u);
    // XLA ErfInv32 (Giles single-precision polynomial)
    float w = -log1pf(-u * u);
    float p;
    if (w < 5.0f) {
        w -= 2.5f;
        p = 2.81022636e-08f;
        p = fmaf(p, w, 3.43273939e-07f);
        p = fmaf(p, w, -3.5233877e-06f);
        p = fmaf(p, w, -4.39150654e-06f);
        p = fmaf(p, w, 0.00021858087f);
        p = fmaf(p, w, -0.00125372503f);
        p = fmaf(p, w, -0.00417768164f);
        p = fmaf(p, w, 0.246640727f);
        p = fmaf(p, w, 1.50140941f);
    } else {
        w = sqrtf(w) - 3.0f;
        p = -0.000200214257f;
        p = fmaf(p, w, 0.000100950558f);
        p = fmaf(p, w, 0.00134934322f);
        p = fmaf(p, w, -0.00367342844f);
        p = fmaf(p, w, 0.00573950773f);
        p = fmaf(p, w, -0.0076224613f);
        p = fmaf(p, w, 0.00943887047f);
        p = fmaf(p, w, 1.00167406f);
        p = fmaf(p, w, 2.83297682f);
    }
    float nrm = 1.41421356f * (p * u);   // f32(sqrt(2)) * erfinv(u)
    return nrm * 0.01f;
}

// ---------------- kernel 0: reset counters, detect nonzero b1 -------------
__global__ void k_setup(const float* __restrict__ b1) {
    int tid = threadIdx.x;
    if (tid < NEXP) g_cnt[tid] = 0;
    if (tid == 0) g_bflag = 0;
    __syncthreads();
    int nz = 0;
    for (int i = tid; i < NEXP * HDIM; i += blockDim.x)
        nz |= (b1[i] != 0.0f);
    if (__syncthreads_or(nz)) { if (tid == 0) g_bflag = 1; }
}

// ---------------- kernel 1: expert output for zero input ------------------
__global__ void k_z(const float* __restrict__ b1, const float* __restrict__ w2,
                    const float* __restrict__ b2) {
    int e = blockIdx.x;
    int d = blockIdx.y * 128 + threadIdx.x;
    if (g_bflag == 0) {               // b1 == 0 -> silu(0)=0 -> z = b2
        g_z[e * DDIM + d] = b2[e * DDIM + d];
        return;
    }
    __shared__ float s1[HDIM];
    for (int i = threadIdx.x; i < HDIM; i += 128) {
        float v = b1[e * HDIM + i];
        s1[i] = v / (1.0f + expf(-v));
    }
    __syncthreads();
    float acc = 0.0f;
    for (int h = 0; h < HDIM; h++)
        acc += s1[h] * w2[((size_t)e * HDIM + h) * DDIM + d];
    g_z[e * DDIM + d] = acc + b2[e * DDIM + d];
}

// ---------------- kernel 2: gate — one block per token, 128 threads -------
__global__ __launch_bounds__(128) void k_gate(
    const float* __restrict__ x, const float* __restrict__ gw,
    const float* __restrict__ gb, float* __restrict__ out,
    int out_size, int T)
{
    __shared__ float xs[DDIM];
    __shared__ float wsum[4];
    __shared__ float ls[NEXP];
    __shared__ float sh_p0, sh_p1;
    __shared__ int   sh_i0, sh_i1;

    int t = blockIdx.x;
    int tid = threadIdx.x, lane = tid & 31, wid = tid >> 5;

    float4 v = ((const float4*)x)[(size_t)t * 128 + tid];
    float s = (v.x + v.y) + (v.z + v.w);
#pragma unroll
    for (int o = 16; o; o >>= 1) s += __shfl_xor_sync(0xffffffffu, s, o);
    if (lane == 0) wsum[wid] = s;
    __syncthreads();
    float sall = (wsum[0] + wsum[1]) + (wsum[2] + wsum[3]);
    int keep = (sall / 512.0f) > 0.1f;
    float denom = sall + 1e-8f;
    float4 xn;
    if (keep) {
        xn = make_float4(v.x / denom, v.y / denom, v.z / denom, v.w / denom);
        ((float4*)g_xn)[(size_t)t * 128 + tid] = xn;
    } else {
        xn = make_float4(0.f, 0.f, 0.f, 0.f);
    }
    ((float4*)xs)[tid] = xn;
    __syncthreads();

    // logits: warp w handles experts 4w..4w+3
#pragma unroll
    for (int ee = 0; ee < 4; ee++) {
        int e = wid * 4 + ee;
        float p = 0.0f;
#pragma unroll
        for (int k2 = 0; k2 < 16; k2++) {
            int d = k2 * 32 + lane;
            p += xs[d] * gw[d * 16 + e];
        }
#pragma unroll
        for (int o = 16; o; o >>= 1) p += __shfl_xor_sync(0xffffffffu, p, o);
        if (lane == 0)
            ls[e] = p + gb[e] + jax_noise((uint32_t)(t * 16 + e));
    }
    __syncthreads();

    if (tid == 0) {
        // top-2 with lax.top_k tie semantics (lowest index first)
        float l0 = ls[0]; int i0 = 0;
#pragma unroll
        for (int e = 1; e < 16; e++) if (ls[e] > l0) { l0 = ls[e]; i0 = e; }
        float l1 = -3.4e38f; int i1 = 0;
#pragma unroll
        for (int e = 0; e < 16; e++)
            if (e != i0 && ls[e] > l1) { l1 = ls[e]; i1 = e; }

        float pr[16]; float sum = 0.0f;
#pragma unroll
        for (int e = 0; e < 16; e++) {
            float vv = (ls[e] >= l1) ? expf(ls[e] - l0) : 0.0f;
            pr[e] = vv; sum += vv;
        }
#pragma unroll
        for (int e = 0; e < 16; e++) g_rp[t * 16 + e] = pr[e] / sum;
        float p0 = pr[i0] / sum, p1 = pr[i1] / sum;

        sh_i0 = i0; sh_i1 = i1; sh_p0 = p0; sh_p1 = p1;
        g_keep[t] = keep;
        if (keep) {
            int a0 = atomicAdd(&g_cnt[i0], 1);
            g_tok[i0*CAP+a0] = t; g_prob[i0*CAP+a0] = p0; g_pair[i0*CAP+a0] = 2*t;
            int a1 = atomicAdd(&g_cnt[i1], 1);
            g_tok[i1*CAP+a1] = t; g_prob[i1*CAP+a1] = p1; g_pair[i1*CAP+a1] = 2*t+1;
        }
        if (out_size >= T * DDIM + 2 * T) {
            out[T * DDIM + 2*t]     = (float)i0;
            out[T * DDIM + 2*t + 1] = (float)i1;
        }
    }
    __syncthreads();

    // inactive token: final = p0*z[i0] + p1*z[i1]  (z = 0 when biases are 0)
    if (!keep) {
        float4 a = ((const float4*)g_z)[sh_i0 * 128 + tid];
        float4 b = ((const float4*)g_z)[sh_i1 * 128 + tid];
        float p0 = sh_p0, p1 = sh_p1;
        ((float4*)out)[(size_t)t * 128 + tid] =
            make_float4(p0*a.x + p1*b.x, p0*a.y + p1*b.y,
                        p0*a.z + p1*b.z, p0*a.w + p1*b.w);
    }
}

// ---------------- kernel 3: active tokens, h = silu(xn @ w1) --------------
__global__ __launch_bounds__(256) void k_gemm1(const float* __restrict__ w1) {
    int e = blockIdx.x;
    int n = g_cnt[e];
    if (n == 0) return;
    int hcol = blockIdx.y * 64 + (threadIdx.x & 63);
    int grp  = threadIdx.x >> 6;       // 0..3

    __shared__ float xsm[16][DDIM];
    __shared__ int toks[16], pairs[16];

    for (int base = 0; base < n; base += 16) {
        int m = min(16, n - base);
        if (threadIdx.x < m) {
            toks[threadIdx.x]  = g_tok [e*CAP + base + threadIdx.x];
            pairs[threadIdx.x] = g_pair[e*CAP + base + threadIdx.x];
        }
        __syncthreads();
        for (int idx = threadIdx.x; idx < m * 128; idx += 256) {
            int r = idx >> 7, c = idx & 127;
            ((float4*)xsm[r])[c] = ((const float4*)(g_xn + (size_t)toks[r] * DDIM))[c];
        }
        __syncthreads();

        const float* wp = w1 + ((size_t)e * DDIM) * HDIM + hcol;
        float acc[4] = {0.f, 0.f, 0.f, 0.f};
#pragma unroll 4
        for (int d = 0; d < DDIM; d += 4) {
            float wa = wp[(size_t)(d+0) * HDIM];
            float wb = wp[(size_t)(d+1) * HDIM];
            float wc = wp[(size_t)(d+2) * HDIM];
            float wd = wp[(size_t)(d+3) * HDIM];
#pragma unroll
            for (int j = 0; j < 4; j++) {
                float4 xv = *(const float4*)&xsm[grp + 4*j][d];
                acc[j] += xv.x*wa + xv.y*wb + xv.z*wc + xv.w*wd;
            }
        }
#pragma unroll
        for (int j = 0; j < 4; j++) {
            int tr = grp + 4*j;
            if (tr < m) {
                float vv = acc[j];
                g_hbuf[(size_t)pairs[tr] * HDIM + hcol] = vv / (1.0f + expf(-vv));
            }
        }
        __syncthreads();
    }
}

// ---------------- kernel 4: contrib[2t+k] = p * (silu_h @ w2 + b2) --------
__global__ __launch_bounds__(256) void k_gemm2(
    const float* __restrict__ w2, const float* __restrict__ b2)
{
    int e = blockIdx.x;
    int n = g_cnt[e];
    if (n == 0) return;
    int dcol = blockIdx.y * 64 + (threadIdx.x & 63);
    int grp  = threadIdx.x >> 6;       // 0..3

    __shared__ float hs[8][HDIM];
    __shared__ int pairs[8];
    __shared__ float probs[8];

    for (int base = 0; base < n; base += 8) {
        int m = min(8, n - base);
        if (threadIdx.x < m) {
            pairs[threadIdx.x] = g_pair[e*CAP + base + threadIdx.x];
            probs[threadIdx.x] = g_prob[e*CAP + base + threadIdx.x];
        }
        __syncthreads();
        for (int idx = threadIdx.x; idx < m * 256; idx += 256) {
            int r = idx >> 8, c = idx & 255;
            ((float4*)hs[r])[c] = ((const float4*)(g_hbuf + (size_t)pairs[r] * HDIM))[c];
        }
        __syncthreads();

        const float* wp = w2 + ((size_t)e * HDIM) * DDIM + dcol;
        float acc[2] = {0.f, 0.f};
#pragma unroll 4
        for (int h = 0; h < HDIM; h += 4) {
            float wa = wp[(size_t)(h+0) * DDIM];
            float wb = wp[(size_t)(h+1) * DDIM];
            float wc = wp[(size_t)(h+2) * DDIM];
            float wd = wp[(size_t)(h+3) * DDIM];
#pragma unroll
            for (int j = 0; j < 2; j++) {
                float4 hv = *(const float4*)&hs[grp + 4*j][h];
                acc[j] += hv.x*wa + hv.y*wb + hv.z*wc + hv.w*wd;
            }
        }
        float bb = b2[e * DDIM + dcol];
#pragma unroll
        for (int j = 0; j < 2; j++) {
            int tr = grp + 4*j;
            if (tr < m)
                g_contrib[(size_t)pairs[tr] * DDIM + dcol] = probs[tr] * (acc[j] + bb);
        }
        __syncthreads();
    }
}

// ---------------- kernel 5: combine active rows (fixed order) -------------
__global__ void k_combine(float* __restrict__ out) {
    int t = blockIdx.x;
    if (!g_keep[t]) return;
    int c = threadIdx.x;               // 128 float4 per row
    float4 a = ((const float4*)g_contrib)[(size_t)(2*t)   * 128 + c];
    float4 b = ((const float4*)g_contrib)[(size_t)(2*t+1) * 128 + c];
    ((float4*)out)[(size_t)t * 128 + c] =
        make_float4(a.x+b.x, a.y+b.y, a.z+b.z, a.w+b.w);
}

// ---------------- kernel 6: aux load-balancing loss -----------------------
__global__ void k_aux(float* __restrict__ out, int out_size, int T) {
    __shared__ float us[16 * 17];
    int e = threadIdx.x & 15, g = threadIdx.x >> 4;
    int rows = T / 16;
    float u = 0.0f;
    for (int r = g * rows; r < (g + 1) * rows; r++)
        u += g_rp[r * 16 + e];
    us[g * 17 + e] = u;
    __syncthreads();
    if (threadIdx.x == 0) {
        float usage[16]; float tot = 0.0f;
        for (int ee = 0; ee < 16; ee++) {
            float v = 0.0f;
            for (int gg = 0; gg < 16; gg++) v += us[gg * 17 + ee];
            usage[ee] = v; tot += v;
        }
        float imp[16]; float mean = 0.0f;
        for (int ee = 0; ee < 16; ee++) { imp[ee] = usage[ee] / (tot + 1e-10f); mean += imp[ee]; }
        mean /= 16.0f;
        float var = 0.0f;
        for (int ee = 0; ee < 16; ee++) { float d = imp[ee] - mean; var += d * d; }
        var /= 16.0f;
        float aux = sqrtf(var) / (mean + 1e-10f);
        if (out_size >= T * DDIM + 2 * T + 1)
            out[T * DDIM + 2 * T] = aux;
    }
}

// ---------------- host launcher -------------------------------------------
extern "C" void kernel_launch(void* const* d_in, const int* in_sizes, int n_in,
                              void* d_out, int out_size) {
    // insertion order confirmed by round-4 diagnostics
    const float* x  = (const float*)d_in[0];
    const float* gw = (const float*)d_in[1];
    const float* gb = (const float*)d_in[2];
    const float* w1 = (const float*)d_in[3];
    const float* b1 = (const float*)d_in[4];
    const float* w2 = (const float*)d_in[5];
    const float* b2 = (const float*)d_in[6];
    float* out = (float*)d_out;
    int T = in_sizes[0] / DDIM;        // 8192

    k_setup  <<<1, 256>>>(b1);
    k_z      <<<dim3(NEXP, 4), 128>>>(b1, w2, b2);
    k_gate   <<<T, 128>>>(x, gw, gb, out, out_size, T);
    k_gemm1  <<<dim3(NEXP, HDIM / 64), 256>>>(w1);
    k_gemm2  <<<dim3(NEXP, DDIM / 64), 256>>>(w2, b2);
    k_combine<<<T, 128>>>(out);
    k_aux    <<<1, 256>>>(out, out_size, T);
}

// round 6
// speedup vs baseline: 3.3418x; 3.3418x over previous
#include <cuda_runtime.h>
#include <cstdint>

// Problem constants
#define NTOK   8192      // B*S = 4*2048
#define DDIM   512
#define NEXP   16
#define HDIM   1024
#define CAP    8192

// ---------------- scratch (device globals: allocation-free) ----------------
__device__ float g_xn[NTOK * DDIM];             // normalized x (active rows only)
__device__ float g_hbuf[(2 * NTOK) * HDIM];     // raw h partial sums (pre-silu)
__device__ float g_contrib[(2 * NTOK) * DDIM];  // raw h@w2 partial sums
__device__ int   g_tok [NEXP * CAP];
__device__ int   g_pair[NEXP * CAP];            // 2t+k
__device__ int   g_keep[NTOK];
__device__ int   g_topi[2 * NTOK];
__device__ float g_topp[2 * NTOK];
__device__ float g_z[NEXP * DDIM];              // expert output for zero input
__device__ float g_usage[NEXP];
__device__ int   g_cnt[NEXP];
__device__ int   g_bflag;

// ---------------- JAX threefry2x32, partitionable path (validated R5) -----
__device__ __forceinline__ uint32_t rotl32(uint32_t x, int r) {
    return (x << r) | (x >> (32 - r));
}

__device__ __forceinline__ void threefry2x32(uint32_t k0, uint32_t k1,
                                             uint32_t& x0, uint32_t& x1) {
    uint32_t k2 = k0 ^ k1 ^ 0x1BD11BDAu;
#define TF_RND(r) { x0 += x1; x1 = rotl32(x1, r); x1 ^= x0; }
    x0 += k0; x1 += k1;
    TF_RND(13) TF_RND(15) TF_RND(26) TF_RND(6)
    x0 += k1; x1 += k2 + 1u;
    TF_RND(17) TF_RND(29) TF_RND(16) TF_RND(24)
    x0 += k2; x1 += k0 + 2u;
    TF_RND(13) TF_RND(15) TF_RND(26) TF_RND(6)
    x0 += k0; x1 += k1 + 3u;
    TF_RND(17) TF_RND(29) TF_RND(16) TF_RND(24)
    x0 += k1; x1 += k2 + 4u;
    TF_RND(13) TF_RND(15) TF_RND(26) TF_RND(6)
    x0 += k2; x1 += k0 + 5u;
#undef TF_RND
}

__device__ __forceinline__ float jax_noise(uint32_t j) {
    uint32_t x0 = 0u, x1 = j;
    threefry2x32(0u, 42u, x0, x1);
    uint32_t bits = x0 ^ x1;
    uint32_t fb = (bits >> 9) | 0x3F800000u;
    float u01 = __uint_as_float(fb) - 1.0f;
    const float minval = __uint_as_float(0xBF7FFFFFu);
    float u = fmaf(u01, 2.0f, minval);
    u = fmaxf(minval, u);
    float w = -log1pf(-u * u);
    float p;
    if (w < 5.0f) {
        w -= 2.5f;
        p = 2.81022636e-08f;
        p = fmaf(p, w, 3.43273939e-07f);
        p = fmaf(p, w, -3.5233877e-06f);
        p = fmaf(p, w, -4.39150654e-06f);
        p = fmaf(p, w, 0.00021858087f);
        p = fmaf(p, w, -0.00125372503f);
        p = fmaf(p, w, -0.00417768164f);
        p = fmaf(p, w, 0.246640727f);
        p = fmaf(p, w, 1.50140941f);
    } else {
        w = sqrtf(w) - 3.0f;
        p = -0.000200214257f;
        p = fmaf(p, w, 0.000100950558f);
        p = fmaf(p, w, 0.00134934322f);
        p = fmaf(p, w, -0.00367342844f);
        p = fmaf(p, w, 0.00573950773f);
        p = fmaf(p, w, -0.0076224613f);
        p = fmaf(p, w, 0.00943887047f);
        p = fmaf(p, w, 1.00167406f);
        p = fmaf(p, w, 2.83297682f);
    }
    float nrm = 1.41421356f * (p * u);
    return nrm * 0.01f;
}

// ---------------- kernel 0: reset counters --------------------------------
__global__ void k_setup(const float* __restrict__ b1) {
    int tid = threadIdx.x;
    if (tid < NEXP) { g_cnt[tid] = 0; g_usage[tid] = 0.0f; }
    if (tid == 0) g_bflag = 0;
    __syncthreads();
    int nz = 0;
    for (int i = tid; i < NEXP * HDIM; i += blockDim.x)
        nz |= (b1[i] != 0.0f);
    if (__syncthreads_or(nz)) { if (tid == 0) g_bflag = 1; }
}

// ---------------- kernel 1: expert output for zero input ------------------
__global__ void k_z(const float* __restrict__ b1, const float* __restrict__ w2,
                    const float* __restrict__ b2) {
    int e = blockIdx.x;
    int d = blockIdx.y * 128 + threadIdx.x;
    if (g_bflag == 0) {               // b1 == 0 -> silu(0)=0 -> z = b2
        g_z[e * DDIM + d] = b2[e * DDIM + d];
        return;
    }
    __shared__ float s1[HDIM];
    for (int i = threadIdx.x; i < HDIM; i += 128) {
        float v = b1[e * HDIM + i];
        s1[i] = v / (1.0f + expf(-v));
    }
    __syncthreads();
    float acc = 0.0f;
    for (int h = 0; h < HDIM; h++)
        acc += s1[h] * w2[((size_t)e * HDIM + h) * DDIM + d];
    g_z[e * DDIM + d] = acc + b2[e * DDIM + d];
}

// ---------------- kernel 2: gate — 16 tokens per block, 256 threads -------
// thread layout for logits: e = tid>>4 (expert), g = tid&15 (d-group)
// thread handles d = g + 16*i for i in [0,32) -> conflict-free xs access.
__global__ __launch_bounds__(256) void k_gate(
    const float* __restrict__ x, const float* __restrict__ gw,
    const float* __restrict__ gb, float* __restrict__ out,
    int out_size, int T)
{
    __shared__ float xs[DDIM];
    __shared__ float wsum[8];
    __shared__ float ls[NEXP];
    __shared__ float us[NEXP];
    __shared__ float sh_p0, sh_p1;
    __shared__ int   sh_i0, sh_i1;

    int tid = threadIdx.x, lane = tid & 31, wid = tid >> 5;
    int e = tid >> 4, g = tid & 15;

    // register-resident gate_w slice: gwr[i] = gw[(g+16i)][e]
    float gwr[32];
#pragma unroll
    for (int i = 0; i < 32; i++)
        gwr[i] = gw[(g + 16 * i) * NEXP + e];

    if (tid < NEXP) us[tid] = 0.0f;

    for (int tt = 0; tt < 16; tt++) {
        int t = blockIdx.x * 16 + tt;

        float2 xv = ((const float2*)x)[(size_t)t * 256 + tid];
        float s = xv.x + xv.y;
#pragma unroll
        for (int o = 16; o; o >>= 1) s += __shfl_xor_sync(0xffffffffu, s, o);
        if (lane == 0) wsum[wid] = s;
        __syncthreads();
        float sall = ((wsum[0] + wsum[1]) + (wsum[2] + wsum[3]))
                   + ((wsum[4] + wsum[5]) + (wsum[6] + wsum[7]));
        int keep = (sall / 512.0f) > 0.1f;
        float denom = sall + 1e-8f;
        float2 xn = keep ? make_float2(xv.x / denom, xv.y / denom)
                         : make_float2(0.f, 0.f);
        if (keep)
            ((float2*)g_xn)[(size_t)t * 256 + tid] = xn;
        xs[2 * tid] = xn.x; xs[2 * tid + 1] = xn.y;
        __syncthreads();

        // logits
        float p = 0.0f;
#pragma unroll
        for (int i = 0; i < 32; i++)
            p += xs[g + 16 * i] * gwr[i];
        p += __shfl_down_sync(0xffffffffu, p, 8, 16);
        p += __shfl_down_sync(0xffffffffu, p, 4, 16);
        p += __shfl_down_sync(0xffffffffu, p, 2, 16);
        p += __shfl_down_sync(0xffffffffu, p, 1, 16);
        if (g == 0)
            ls[e] = p + gb[e] + jax_noise((uint32_t)(t * 16 + e));
        __syncthreads();

        if (tid == 0) {
            float l0 = ls[0]; int i0 = 0;
#pragma unroll
            for (int ee = 1; ee < 16; ee++) if (ls[ee] > l0) { l0 = ls[ee]; i0 = ee; }
            float l1 = -3.4e38f; int i1 = 0;
#pragma unroll
            for (int ee = 0; ee < 16; ee++)
                if (ee != i0 && ls[ee] > l1) { l1 = ls[ee]; i1 = ee; }

            float pr[16]; float sum = 0.0f;
#pragma unroll
            for (int ee = 0; ee < 16; ee++) {
                float vv = (ls[ee] >= l1) ? expf(ls[ee] - l0) : 0.0f;
                pr[ee] = vv; sum += vv;
            }
            float inv = 1.0f / sum;
#pragma unroll
            for (int ee = 0; ee < 16; ee++) us[ee] += pr[ee] * inv;
            float p0 = pr[i0] * inv, p1 = pr[i1] * inv;

            sh_i0 = i0; sh_i1 = i1; sh_p0 = p0; sh_p1 = p1;
            g_keep[t] = keep;
            g_topi[2*t] = i0; g_topi[2*t+1] = i1;
            g_topp[2*t] = p0; g_topp[2*t+1] = p1;
            if (keep) {
                int a0 = atomicAdd(&g_cnt[i0], 1);
                g_tok[i0*CAP+a0] = t; g_pair[i0*CAP+a0] = 2*t;
                int a1 = atomicAdd(&g_cnt[i1], 1);
                g_tok[i1*CAP+a1] = t; g_pair[i1*CAP+a1] = 2*t+1;
            }
            if (out_size >= T * DDIM + 2 * T) {
                out[T * DDIM + 2*t]     = (float)i0;
                out[T * DDIM + 2*t + 1] = (float)i1;
            }
        }
        __syncthreads();

        // inactive token: final = p0*z[i0] + p1*z[i1]
        if (!keep) {
            float2 a = ((const float2*)g_z)[sh_i0 * 256 + tid];
            float2 b = ((const float2*)g_z)[sh_i1 * 256 + tid];
            float p0 = sh_p0, p1 = sh_p1;
            ((float2*)out)[(size_t)t * 256 + tid] =
                make_float2(p0*a.x + p1*b.x, p0*a.y + p1*b.y);
        }
    }
    __syncthreads();
    if (tid < NEXP) atomicAdd(&g_usage[tid], us[tid]);
}

// ---------------- kernel 3: zero staging rows of active tokens ------------
__global__ void k_zero() {
    int t = blockIdx.x;
    if (!g_keep[t]) return;
    int tid = threadIdx.x;             // 128
    float4 z4 = make_float4(0.f, 0.f, 0.f, 0.f);
    float4* h = (float4*)(g_hbuf + (size_t)(2*t) * HDIM);      // 512 float4
    for (int i = tid; i < 512; i += 128) h[i] = z4;
    float4* c = (float4*)(g_contrib + (size_t)(2*t) * DDIM);   // 256 float4
    for (int i = tid; i < 256; i += 128) c[i] = z4;
}

// ---------------- kernel 4: h partials = xn @ w1 (d-split, atomics) -------
// grid (16, HDIM/128=8, DDIM/128=4), 256 threads: c=tid&127 (h col),
// half=tid>>7 (two 64-wide d sub-ranges). 16-token tiles, acc[16] in regs.
__global__ __launch_bounds__(256) void k_gemm1(const float* __restrict__ w1) {
    int e = blockIdx.x;
    int n = g_cnt[e];
    if (n == 0) return;
    int hc0 = blockIdx.y * 128;
    int d0  = blockIdx.z * 128;
    int c = threadIdx.x & 127, half = threadIdx.x >> 7;

    __shared__ float xs[16][128];
    __shared__ int toks[16], pairs[16];

    for (int base = 0; base < n; base += 16) {
        int m = min(16, n - base);
        if (threadIdx.x < m) {
            toks[threadIdx.x]  = g_tok [e*CAP + base + threadIdx.x];
            pairs[threadIdx.x] = g_pair[e*CAP + base + threadIdx.x];
        }
        __syncthreads();
        for (int idx = threadIdx.x; idx < m * 32; idx += 256) {
            int r = idx >> 5, cc = idx & 31;
            ((float4*)xs[r])[cc] =
                ((const float4*)(g_xn + (size_t)toks[r] * DDIM + d0))[cc];
        }
        __syncthreads();

        const float* wp = w1 + ((size_t)e * DDIM + d0 + half * 64) * HDIM + hc0 + c;
        float acc[16];
#pragma unroll
        for (int j = 0; j < 16; j++) acc[j] = 0.0f;
#pragma unroll 4
        for (int dd = 0; dd < 64; dd++) {
            float wv = wp[(size_t)dd * HDIM];
#pragma unroll
            for (int j = 0; j < 16; j++)
                acc[j] = fmaf(xs[j][half * 64 + dd], wv, acc[j]);
        }
        for (int j = 0; j < m; j++)
            atomicAdd(&g_hbuf[(size_t)pairs[j] * HDIM + hc0 + c], acc[j]);
        __syncthreads();
    }
}

// ---------------- kernel 5: contrib partials = silu(h) @ w2 (k-split) -----
// grid (16, DDIM/128=4, HDIM/128=8), 256 threads: c=tid&127 (d col),
// half=tid>>7 (two 64-wide k sub-ranges). silu applied at tile load.
__global__ __launch_bounds__(256) void k_gemm2(const float* __restrict__ w2) {
    int e = blockIdx.x;
    int n = g_cnt[e];
    if (n == 0) return;
    int dc0 = blockIdx.y * 128;
    int k0  = blockIdx.z * 128;
    int c = threadIdx.x & 127, half = threadIdx.x >> 7;

    __shared__ float hs[16][128];
    __shared__ int pairs[16];

    for (int base = 0; base < n; base += 16) {
        int m = min(16, n - base);
        if (threadIdx.x < m)
            pairs[threadIdx.x] = g_pair[e*CAP + base + threadIdx.x];
        __syncthreads();
        for (int idx = threadIdx.x; idx < m * 32; idx += 256) {
            int r = idx >> 5, cc = idx & 31;
            float4 v = ((const float4*)(g_hbuf + (size_t)pairs[r] * HDIM + k0))[cc];
            v.x = v.x / (1.0f + expf(-v.x));
            v.y = v.y / (1.0f + expf(-v.y));
            v.z = v.z / (1.0f + expf(-v.z));
            v.w = v.w / (1.0f + expf(-v.w));
            ((float4*)hs[r])[cc] = v;
        }
        __syncthreads();

        const float* wp = w2 + ((size_t)e * HDIM + k0 + half * 64) * DDIM + dc0 + c;
        float acc[16];
#pragma unroll
        for (int j = 0; j < 16; j++) acc[j] = 0.0f;
#pragma unroll 4
        for (int kk = 0; kk < 64; kk++) {
            float wv = wp[(size_t)kk * DDIM];
#pragma unroll
            for (int j = 0; j < 16; j++)
                acc[j] = fmaf(hs[j][half * 64 + kk], wv, acc[j]);
        }
        for (int j = 0; j < m; j++)
            atomicAdd(&g_contrib[(size_t)pairs[j] * DDIM + dc0 + c], acc[j]);
        __syncthreads();
    }
}

// ---------------- kernel 6: combine active rows ---------------------------
__global__ void k_combine(const float* __restrict__ b2, float* __restrict__ out) {
    int t = blockIdx.x;
    if (!g_keep[t]) return;
    int c = threadIdx.x;               // 128 float4 per row
    int i0 = g_topi[2*t], i1 = g_topi[2*t+1];
    float p0 = g_topp[2*t], p1 = g_topp[2*t+1];
    float4 a = ((const float4*)(g_contrib + (size_t)(2*t)   * DDIM))[c];
    float4 b = ((const float4*)(g_contrib + (size_t)(2*t+1) * DDIM))[c];
    float4 ba = ((const float4*)(b2 + (size_t)i0 * DDIM))[c];
    float4 bb = ((const float4*)(b2 + (size_t)i1 * DDIM))[c];
    ((float4*)out)[(size_t)t * 128 + c] = make_float4(
        p0*(a.x+ba.x) + p1*(b.x+bb.x),
        p0*(a.y+ba.y) + p1*(b.y+bb.y),
        p0*(a.z+ba.z) + p1*(b.z+bb.z),
        p0*(a.w+ba.w) + p1*(b.w+bb.w));
}

// ---------------- kernel 7: aux from usage --------------------------------
__global__ void k_aux(float* __restrict__ out, int out_size, int T) {
    if (threadIdx.x != 0) return;
    float usage[16]; float tot = 0.0f;
    for (int e = 0; e < 16; e++) { usage[e] = g_usage[e]; tot += usage[e]; }
    float imp[16]; float mean = 0.0f;
    for (int e = 0; e < 16; e++) { imp[e] = usage[e] / (tot + 1e-10f); mean += imp[e]; }
    mean /= 16.0f;
    float var = 0.0f;
    for (int e = 0; e < 16; e++) { float d = imp[e] - mean; var += d * d; }
    var /= 16.0f;
    float aux = sqrtf(var) / (mean + 1e-10f);
    if (out_size >= T * DDIM + 2 * T + 1)
        out[T * DDIM + 2 * T] = aux;
}

// ---------------- host launcher -------------------------------------------
extern "C" void kernel_launch(void* const* d_in, const int* in_sizes, int n_in,
                              void* d_out, int out_size) {
    const float* x  = (const float*)d_in[0];
    const float* gw = (const float*)d_in[1];
    const float* gb = (const float*)d_in[2];
    const float* w1 = (const float*)d_in[3];
    const float* b1 = (const float*)d_in[4];
    const float* w2 = (const float*)d_in[5];
    const float* b2 = (const float*)d_in[6];
    float* out = (float*)d_out;
    int T = in_sizes[0] / DDIM;        // 8192

    k_setup  <<<1, 256>>>(b1);
    k_z      <<<dim3(NEXP, 4), 128>>>(b1, w2, b2);
    k_gate   <<<T / 16, 256>>>(x, gw, gb, out, out_size, T);
    k_zero   <<<T, 128>>>();
    k_gemm1  <<<dim3(NEXP, 8, 4), 256>>>(w1);
    k_gemm2  <<<dim3(NEXP, 4, 8), 256>>>(w2);
    k_combine<<<T, 128>>>(b2, out);
    k_aux    <<<1, 32>>>(out, out_size, T);
}

// round 7
// speedup vs baseline: 4.3571x; 1.3039x over previous
#include <cuda_runtime.h>
#include <cstdint>

// Problem constants
#define NTOK   8192      // B*S = 4*2048
#define DDIM   512
#define NEXP   16
#define HDIM   1024
#define CAP    8192

// ---------------- scratch (device globals: allocation-free) ----------------
__device__ float g_xn[NTOK * DDIM];             // normalized x (active rows only)
__device__ float g_hbuf[(2 * NTOK) * HDIM];     // raw h partial sums (pre-silu)
__device__ float g_contrib[(2 * NTOK) * DDIM];  // raw h@w2 partial sums
__device__ int   g_tok [NEXP * CAP];
__device__ int   g_pair[NEXP * CAP];            // 2t+k
__device__ int   g_keep[NTOK];
__device__ int   g_topi[2 * NTOK];
__device__ float g_topp[2 * NTOK];
__device__ int   g_act[NTOK];                   // compacted active-token list
__device__ float g_z[NEXP * DDIM];              // expert output for zero input
__device__ float g_usage[NEXP];
__device__ int   g_cnt[NEXP];
__device__ int   g_nact;
__device__ int   g_bflag;

// ---------------- JAX threefry2x32, partitionable path (validated R5) -----
__device__ __forceinline__ uint32_t rotl32(uint32_t x, int r) {
    return (x << r) | (x >> (32 - r));
}

__device__ __forceinline__ void threefry2x32(uint32_t k0, uint32_t k1,
                                             uint32_t& x0, uint32_t& x1) {
    uint32_t k2 = k0 ^ k1 ^ 0x1BD11BDAu;
#define TF_RND(r) { x0 += x1; x1 = rotl32(x1, r); x1 ^= x0; }
    x0 += k0; x1 += k1;
    TF_RND(13) TF_RND(15) TF_RND(26) TF_RND(6)
    x0 += k1; x1 += k2 + 1u;
    TF_RND(17) TF_RND(29) TF_RND(16) TF_RND(24)
    x0 += k2; x1 += k0 + 2u;
    TF_RND(13) TF_RND(15) TF_RND(26) TF_RND(6)
    x0 += k0; x1 += k1 + 3u;
    TF_RND(17) TF_RND(29) TF_RND(16) TF_RND(24)
    x0 += k1; x1 += k2 + 4u;
    TF_RND(13) TF_RND(15) TF_RND(26) TF_RND(6)
    x0 += k2; x1 += k0 + 5u;
#undef TF_RND
}

__device__ __forceinline__ float jax_noise(uint32_t j) {
    uint32_t x0 = 0u, x1 = j;
    threefry2x32(0u, 42u, x0, x1);
    uint32_t bits = x0 ^ x1;
    uint32_t fb = (bits >> 9) | 0x3F800000u;
    float u01 = __uint_as_float(fb) - 1.0f;
    const float minval = __uint_as_float(0xBF7FFFFFu);
    float u = fmaf(u01, 2.0f, minval);
    u = fmaxf(minval, u);
    float w = -log1pf(-u * u);
    float p;
    if (w < 5.0f) {
        w -= 2.5f;
        p = 2.81022636e-08f;
        p = fmaf(p, w, 3.43273939e-07f);
        p = fmaf(p, w, -3.5233877e-06f);
        p = fmaf(p, w, -4.39150654e-06f);
        p = fmaf(p, w, 0.00021858087f);
        p = fmaf(p, w, -0.00125372503f);
        p = fmaf(p, w, -0.00417768164f);
        p = fmaf(p, w, 0.246640727f);
        p = fmaf(p, w, 1.50140941f);
    } else {
        w = sqrtf(w) - 3.0f;
        p = -0.000200214257f;
        p = fmaf(p, w, 0.000100950558f);
        p = fmaf(p, w, 0.00134934322f);
        p = fmaf(p, w, -0.00367342844f);
        p = fmaf(p, w, 0.00573950773f);
        p = fmaf(p, w, -0.0076224613f);
        p = fmaf(p, w, 0.00943887047f);
        p = fmaf(p, w, 1.00167406f);
        p = fmaf(p, w, 2.83297682f);
    }
    float nrm = 1.41421356f * (p * u);
    return nrm * 0.01f;
}

// ---------------- kernel 0: reset counters --------------------------------
__global__ void k_setup(const float* __restrict__ b1) {
    int tid = threadIdx.x;
    if (tid < NEXP) { g_cnt[tid] = 0; g_usage[tid] = 0.0f; }
    if (tid == 0) { g_bflag = 0; g_nact = 0; }
    __syncthreads();
    int nz = 0;
    for (int i = tid; i < NEXP * HDIM; i += blockDim.x)
        nz |= (b1[i] != 0.0f);
    if (__syncthreads_or(nz)) { if (tid == 0) g_bflag = 1; }
}

// ---------------- kernel 1: expert output for zero input ------------------
__global__ void k_z(const float* __restrict__ b1, const float* __restrict__ w2,
                    const float* __restrict__ b2) {
    int e = blockIdx.x;
    int d = blockIdx.y * 128 + threadIdx.x;
    if (g_bflag == 0) {               // b1 == 0 -> silu(0)=0 -> z = b2
        g_z[e * DDIM + d] = b2[e * DDIM + d];
        return;
    }
    __shared__ float s1[HDIM];
    for (int i = threadIdx.x; i < HDIM; i += 128) {
        float v = b1[e * HDIM + i];
        s1[i] = v / (1.0f + expf(-v));
    }
    __syncthreads();
    float acc = 0.0f;
    for (int h = 0; h < HDIM; h++)
        acc += s1[h] * w2[((size_t)e * HDIM + h) * DDIM + d];
    g_z[e * DDIM + d] = acc + b2[e * DDIM + d];
}

// ---------------- kernel 2: gate — 16 tokens/block, parallel epilogue -----
__global__ __launch_bounds__(256) void k_gate(
    const float* __restrict__ x, const float* __restrict__ gw,
    const float* __restrict__ gb, float* __restrict__ out,
    int out_size, int T)
{
    __shared__ float xs[DDIM];
    __shared__ float wsum[8];
    __shared__ float ls[NEXP];
    __shared__ float us[NEXP];
    __shared__ float sh_p0, sh_p1;
    __shared__ int   sh_i0, sh_i1;

    int tid = threadIdx.x, lane = tid & 31, wid = tid >> 5;
    int e = tid >> 4, g = tid & 15;

    // register-resident gate_w slice: gwr[i] = gw[(g+16i)][e]
    float gwr[32];
#pragma unroll
    for (int i = 0; i < 32; i++)
        gwr[i] = gw[(g + 16 * i) * NEXP + e];

    float gbe = (tid < NEXP) ? gb[tid] : 0.0f;
    if (tid < NEXP) us[tid] = 0.0f;

    for (int tt = 0; tt < 16; tt++) {
        int t = blockIdx.x * 16 + tt;

        float2 xv = ((const float2*)x)[(size_t)t * 256 + tid];
        float s = xv.x + xv.y;
#pragma unroll
        for (int o = 16; o; o >>= 1) s += __shfl_xor_sync(0xffffffffu, s, o);
        if (lane == 0) wsum[wid] = s;
        __syncthreads();                                       // S1
        float sall = ((wsum[0] + wsum[1]) + (wsum[2] + wsum[3]))
                   + ((wsum[4] + wsum[5]) + (wsum[6] + wsum[7]));
        int keep = (sall / 512.0f) > 0.1f;
        float denom = sall + 1e-8f;
        float2 xn = keep ? make_float2(xv.x / denom, xv.y / denom)
                         : make_float2(0.f, 0.f);
        if (keep)
            ((float2*)g_xn)[(size_t)t * 256 + tid] = xn;
        xs[2 * tid] = xn.x; xs[2 * tid + 1] = xn.y;
        __syncthreads();                                       // S2

        // logits: expert e = tid>>4, d-group g = tid&15
        float p = 0.0f;
#pragma unroll
        for (int i = 0; i < 32; i++)
            p += xs[g + 16 * i] * gwr[i];
        p += __shfl_down_sync(0xffffffffu, p, 8, 16);
        p += __shfl_down_sync(0xffffffffu, p, 4, 16);
        p += __shfl_down_sync(0xffffffffu, p, 2, 16);
        p += __shfl_down_sync(0xffffffffu, p, 1, 16);
        if (g == 0)
            ls[e] = p + gbe + jax_noise((uint32_t)(t * 16 + e));
        __syncthreads();                                       // S3

        // parallel top-2 + softmax on lanes 0..15
        if (tid < 16) {
            float l = ls[tid];
            // argmax (ties -> lowest index, matching lax.top_k)
            float m1 = l; int am = tid;
#pragma unroll
            for (int o = 8; o; o >>= 1) {
                float om = __shfl_xor_sync(0xffffu, m1, o, 16);
                int   oa = __shfl_xor_sync(0xffffu, am, o, 16);
                if (om > m1 || (om == m1 && oa < am)) { m1 = om; am = oa; }
            }
            float lx = (tid == am) ? -3.4e38f : l;
            float m2 = lx; int am2 = tid;
#pragma unroll
            for (int o = 8; o; o >>= 1) {
                float om = __shfl_xor_sync(0xffffu, m2, o, 16);
                int   oa = __shfl_xor_sync(0xffffu, am2, o, 16);
                if (om > m2 || (om == m2 && oa < am2)) { m2 = om; am2 = oa; }
            }
            float pe = (l >= m2) ? expf(l - m1) : 0.0f;
            float sum = pe;
#pragma unroll
            for (int o = 8; o; o >>= 1) sum += __shfl_xor_sync(0xffffu, sum, o, 16);
            float pn = pe / sum;
            us[tid] += pn;
            float p0 = __shfl_sync(0xffffu, pn, am, 16);
            float p1 = __shfl_sync(0xffffu, pn, am2, 16);
            if (tid == 0) {
                sh_i0 = am; sh_i1 = am2; sh_p0 = p0; sh_p1 = p1;
                g_keep[t] = keep;
                g_topi[2*t] = am; g_topi[2*t+1] = am2;
                g_topp[2*t] = p0; g_topp[2*t+1] = p1;
                if (keep) {
                    int ia = atomicAdd(&g_nact, 1);
                    g_act[ia] = t;
                    int a0 = atomicAdd(&g_cnt[am], 1);
                    g_tok[am*CAP+a0] = t;  g_pair[am*CAP+a0] = 2*t;
                    int a1 = atomicAdd(&g_cnt[am2], 1);
                    g_tok[am2*CAP+a1] = t; g_pair[am2*CAP+a1] = 2*t+1;
                }
                if (out_size >= T * DDIM + 2 * T) {
                    out[T * DDIM + 2*t]     = (float)am;
                    out[T * DDIM + 2*t + 1] = (float)am2;
                }
            }
        }
        __syncthreads();                                       // S4

        if (!keep) {
            // inactive token: final = p0*z[i0] + p1*z[i1]
            float2 a = ((const float2*)g_z)[sh_i0 * 256 + tid];
            float2 b = ((const float2*)g_z)[sh_i1 * 256 + tid];
            float p0 = sh_p0, p1 = sh_p1;
            ((float2*)out)[(size_t)t * 256 + tid] =
                make_float2(p0*a.x + p1*b.x, p0*a.y + p1*b.y);
        } else {
            // zero the two staging rows for this token's assignments
            float4 z4 = make_float4(0.f, 0.f, 0.f, 0.f);
            float4* h4 = (float4*)(g_hbuf + (size_t)(2*t) * HDIM);     // 512 f4
#pragma unroll
            for (int i = 0; i < 2; i++) h4[tid + 256 * i] = z4;
            float4* c4 = (float4*)(g_contrib + (size_t)(2*t) * DDIM);  // 256 f4
            c4[tid] = z4;
        }
    }
    __syncthreads();
    if (tid < NEXP) atomicAdd(&g_usage[tid], us[tid]);
}

// ---------------- kernel 3: h partials = xn @ w1 (d-split, atomics) -------
__global__ __launch_bounds__(256) void k_gemm1(const float* __restrict__ w1) {
    int e = blockIdx.x;
    int n = g_cnt[e];
    if (n == 0) return;
    int hc0 = blockIdx.y * 128;
    int d0  = blockIdx.z * 128;
    int c = threadIdx.x & 127, half = threadIdx.x >> 7;

    __shared__ float xs[16][128];
    __shared__ int toks[16], pairs[16];

    for (int base = 0; base < n; base += 16) {
        int m = min(16, n - base);
        if (threadIdx.x < m) {
            toks[threadIdx.x]  = g_tok [e*CAP + base + threadIdx.x];
            pairs[threadIdx.x] = g_pair[e*CAP + base + threadIdx.x];
        }
        __syncthreads();
        for (int idx = threadIdx.x; idx < m * 32; idx += 256) {
            int r = idx >> 5, cc = idx & 31;
            ((float4*)xs[r])[cc] =
                ((const float4*)(g_xn + (size_t)toks[r] * DDIM + d0))[cc];
        }
        __syncthreads();

        const float* wp = w1 + ((size_t)e * DDIM + d0 + half * 64) * HDIM + hc0 + c;
        float acc[16];
#pragma unroll
        for (int j = 0; j < 16; j++) acc[j] = 0.0f;
#pragma unroll 4
        for (int dd = 0; dd < 64; dd++) {
            float wv = wp[(size_t)dd * HDIM];
#pragma unroll
            for (int j = 0; j < 16; j++)
                acc[j] = fmaf(xs[j][half * 64 + dd], wv, acc[j]);
        }
        for (int j = 0; j < m; j++)
            atomicAdd(&g_hbuf[(size_t)pairs[j] * HDIM + hc0 + c], acc[j]);
        __syncthreads();
    }
}

// ---------------- kernel 4: contrib partials = silu(h) @ w2 (k-split) -----
__global__ __launch_bounds__(256) void k_gemm2(const float* __restrict__ w2) {
    int e = blockIdx.x;
    int n = g_cnt[e];
    if (n == 0) return;
    int dc0 = blockIdx.y * 128;
    int k0  = blockIdx.z * 128;
    int c = threadIdx.x & 127, half = threadIdx.x >> 7;

    __shared__ float hs[16][128];
    __shared__ int pairs[16];

    for (int base = 0; base < n; base += 16) {
        int m = min(16, n - base);
        if (threadIdx.x < m)
            pairs[threadIdx.x] = g_pair[e*CAP + base + threadIdx.x];
        __syncthreads();
        for (int idx = threadIdx.x; idx < m * 32; idx += 256) {
            int r = idx >> 5, cc = idx & 31;
            float4 v = ((const float4*)(g_hbuf + (size_t)pairs[r] * HDIM + k0))[cc];
            v.x = v.x / (1.0f + expf(-v.x));
            v.y = v.y / (1.0f + expf(-v.y));
            v.z = v.z / (1.0f + expf(-v.z));
            v.w = v.w / (1.0f + expf(-v.w));
            ((float4*)hs[r])[cc] = v;
        }
        __syncthreads();

        const float* wp = w2 + ((size_t)e * HDIM + k0 + half * 64) * DDIM + dc0 + c;
        float acc[16];
#pragma unroll
        for (int j = 0; j < 16; j++) acc[j] = 0.0f;
#pragma unroll 4
        for (int kk = 0; kk < 64; kk++) {
            float wv = wp[(size_t)kk * DDIM];
#pragma unroll
            for (int j = 0; j < 16; j++)
                acc[j] = fmaf(hs[j][half * 64 + kk], wv, acc[j]);
        }
        for (int j = 0; j < m; j++)
            atomicAdd(&g_contrib[(size_t)pairs[j] * DDIM + dc0 + c], acc[j]);
        __syncthreads();
    }
}

// ---------------- kernel 5: combine active rows (compacted) ---------------
__global__ void k_combine(const float* __restrict__ b2, float* __restrict__ out) {
    int c = threadIdx.x;               // 128 float4 per row
    int na = g_nact;
    for (int i = blockIdx.x; i < na; i += gridDim.x) {
        int t = g_act[i];
        int i0 = g_topi[2*t], i1 = g_topi[2*t+1];
        float p0 = g_topp[2*t], p1 = g_topp[2*t+1];
        float4 a = ((const float4*)(g_contrib + (size_t)(2*t)   * DDIM))[c];
        float4 b = ((const float4*)(g_contrib + (size_t)(2*t+1) * DDIM))[c];
        float4 ba = ((const float4*)(b2 + (size_t)i0 * DDIM))[c];
        float4 bb = ((const float4*)(b2 + (size_t)i1 * DDIM))[c];
        ((float4*)out)[(size_t)t * 128 + c] = make_float4(
            p0*(a.x+ba.x) + p1*(b.x+bb.x),
            p0*(a.y+ba.y) + p1*(b.y+bb.y),
            p0*(a.z+ba.z) + p1*(b.z+bb.z),
            p0*(a.w+ba.w) + p1*(b.w+bb.w));
    }
}

// ---------------- kernel 6: aux from usage --------------------------------
__global__ void k_aux(float* __restrict__ out, int out_size, int T) {
    if (threadIdx.x != 0) return;
    float usage[16]; float tot = 0.0f;
    for (int e = 0; e < 16; e++) { usage[e] = g_usage[e]; tot += usage[e]; }
    float imp[16]; float mean = 0.0f;
    for (int e = 0; e < 16; e++) { imp[e] = usage[e] / (tot + 1e-10f); mean += imp[e]; }
    mean /= 16.0f;
    float var = 0.0f;
    for (int e = 0; e < 16; e++) { float d = imp[e] - mean; var += d * d; }
    var /= 16.0f;
    float aux = sqrtf(var) / (mean + 1e-10f);
    if (out_size >= T * DDIM + 2 * T + 1)
        out[T * DDIM + 2 * T] = aux;
}

// ---------------- host launcher -------------------------------------------
extern "C" void kernel_launch(void* const* d_in, const int* in_sizes, int n_in,
                              void* d_out, int out_size) {
    const float* x  = (const float*)d_in[0];
    const float* gw = (const float*)d_in[1];
    const float* gb = (const float*)d_in[2];
    const float* w1 = (const float*)d_in[3];
    const float* b1 = (const float*)d_in[4];
    const float* w2 = (const float*)d_in[5];
    const float* b2 = (const float*)d_in[6];
    float* out = (float*)d_out;
    int T = in_sizes[0] / DDIM;        // 8192

    k_setup  <<<1, 256>>>(b1);
    k_z      <<<dim3(NEXP, 4), 128>>>(b1, w2, b2);
    k_gate   <<<T / 16, 256>>>(x, gw, gb, out, out_size, T);
    k_gemm1  <<<dim3(NEXP, 8, 4), 256>>>(w1);
    k_gemm2  <<<dim3(NEXP, 4, 8), 256>>>(w2);
    k_combine<<<256, 128>>>(b2, out);
    k_aux    <<<1, 32>>>(out, out_size, T);
}

// round 8
// speedup vs baseline: 4.4364x; 1.0182x over previous
#include <cuda_runtime.h>
#include <cstdint>

// Problem constants
#define NTOK   8192      // B*S = 4*2048
#define DDIM   512
#define NEXP   16
#define HDIM   1024
#define CAP    8192

// ---------------- scratch (device globals: allocation-free) ----------------
__device__ float g_xn[NTOK * DDIM];             // normalized x (active rows only)
__device__ float g_hbuf[(2 * NTOK) * HDIM];     // raw h partial sums (pre-silu)
__device__ float g_contrib[(2 * NTOK) * DDIM];  // raw h@w2 partial sums
__device__ int   g_tok [NEXP * CAP];
__device__ int   g_pair[NEXP * CAP];            // 2t+k
__device__ int   g_keep[NTOK];
__device__ int   g_topi[2 * NTOK];
__device__ float g_topp[2 * NTOK];
__device__ int   g_act[NTOK];                   // compacted active-token list
__device__ float g_z[NEXP * DDIM];              // expert output for zero input
__device__ float g_usage[NEXP];
__device__ int   g_cnt[NEXP];
__device__ int   g_nact;
__device__ int   g_bflag;

// ---------------- JAX threefry2x32, partitionable path (validated R5) -----
__device__ __forceinline__ uint32_t rotl32(uint32_t x, int r) {
    return (x << r) | (x >> (32 - r));
}

__device__ __forceinline__ void threefry2x32(uint32_t k0, uint32_t k1,
                                             uint32_t& x0, uint32_t& x1) {
    uint32_t k2 = k0 ^ k1 ^ 0x1BD11BDAu;
#define TF_RND(r) { x0 += x1; x1 = rotl32(x1, r); x1 ^= x0; }
    x0 += k0; x1 += k1;
    TF_RND(13) TF_RND(15) TF_RND(26) TF_RND(6)
    x0 += k1; x1 += k2 + 1u;
    TF_RND(17) TF_RND(29) TF_RND(16) TF_RND(24)
    x0 += k2; x1 += k0 + 2u;
    TF_RND(13) TF_RND(15) TF_RND(26) TF_RND(6)
    x0 += k0; x1 += k1 + 3u;
    TF_RND(17) TF_RND(29) TF_RND(16) TF_RND(24)
    x0 += k1; x1 += k2 + 4u;
    TF_RND(13) TF_RND(15) TF_RND(26) TF_RND(6)
    x0 += k2; x1 += k0 + 5u;
#undef TF_RND
}

__device__ __forceinline__ float jax_noise(uint32_t j) {
    uint32_t x0 = 0u, x1 = j;
    threefry2x32(0u, 42u, x0, x1);
    uint32_t bits = x0 ^ x1;
    uint32_t fb = (bits >> 9) | 0x3F800000u;
    float u01 = __uint_as_float(fb) - 1.0f;
    const float minval = __uint_as_float(0xBF7FFFFFu);
    float u = fmaf(u01, 2.0f, minval);
    u = fmaxf(minval, u);
    float w = -log1pf(-u * u);
    float p;
    if (w < 5.0f) {
        w -= 2.5f;
        p = 2.81022636e-08f;
        p = fmaf(p, w, 3.43273939e-07f);
        p = fmaf(p, w, -3.5233877e-06f);
        p = fmaf(p, w, -4.39150654e-06f);
        p = fmaf(p, w, 0.00021858087f);
        p = fmaf(p, w, -0.00125372503f);
        p = fmaf(p, w, -0.00417768164f);
        p = fmaf(p, w, 0.246640727f);
        p = fmaf(p, w, 1.50140941f);
    } else {
        w = sqrtf(w) - 3.0f;
        p = -0.000200214257f;
        p = fmaf(p, w, 0.000100950558f);
        p = fmaf(p, w, 0.00134934322f);
        p = fmaf(p, w, -0.00367342844f);
        p = fmaf(p, w, 0.00573950773f);
        p = fmaf(p, w, -0.0076224613f);
        p = fmaf(p, w, 0.00943887047f);
        p = fmaf(p, w, 1.00167406f);
        p = fmaf(p, w, 2.83297682f);
    }
    float nrm = 1.41421356f * (p * u);
    return nrm * 0.01f;
}

// ---------------- kernel 0: reset counters --------------------------------
__global__ void k_setup(const float* __restrict__ b1) {
    int tid = threadIdx.x;
    if (tid < NEXP) { g_cnt[tid] = 0; g_usage[tid] = 0.0f; }
    if (tid == 0) { g_bflag = 0; g_nact = 0; }
    __syncthreads();
    int nz = 0;
    for (int i = tid; i < NEXP * HDIM; i += blockDim.x)
        nz |= (b1[i] != 0.0f);
    if (__syncthreads_or(nz)) { if (tid == 0) g_bflag = 1; }
}

// ---------------- kernel 1: expert output for zero input ------------------
__global__ void k_z(const float* __restrict__ b1, const float* __restrict__ w2,
                    const float* __restrict__ b2) {
    int e = blockIdx.x;
    int d = blockIdx.y * 128 + threadIdx.x;
    if (g_bflag == 0) {               // b1 == 0 -> silu(0)=0 -> z = b2
        g_z[e * DDIM + d] = b2[e * DDIM + d];
        return;
    }
    __shared__ float s1[HDIM];
    for (int i = threadIdx.x; i < HDIM; i += 128) {
        float v = b1[e * HDIM + i];
        s1[i] = v / (1.0f + expf(-v));
    }
    __syncthreads();
    float acc = 0.0f;
    for (int h = 0; h < HDIM; h++)
        acc += s1[h] * w2[((size_t)e * HDIM + h) * DDIM + d];
    g_z[e * DDIM + d] = acc + b2[e * DDIM + d];
}

// ---------------- kernel 2: gate — smem-prefetched 16 tokens/block --------
__global__ __launch_bounds__(256) void k_gate(
    const float* __restrict__ x, const float* __restrict__ gw,
    const float* __restrict__ gb, float* __restrict__ out,
    int out_size, int T)
{
    __shared__ float xsall[16][DDIM];     // 32 KB: raw, then normalized in place
    __shared__ float wsum[8];
    __shared__ float ls[NEXP];
    __shared__ float us[NEXP];
    __shared__ float sh_p0, sh_p1;
    __shared__ int   sh_i0, sh_i1;

    int tid = threadIdx.x, lane = tid & 31, wid = tid >> 5;
    int e = tid >> 4, g = tid & 15;

    // register-resident gate_w slice: gwr[i] = gw[(g+16i)][e]
    float gwr[32];
#pragma unroll
    for (int i = 0; i < 32; i++)
        gwr[i] = gw[(g + 16 * i) * NEXP + e];

    float gbe = (tid < NEXP) ? gb[tid] : 0.0f;
    if (tid < NEXP) us[tid] = 0.0f;

    // prefetch all 16 token rows (MLP = 16)
    {
        int t0 = blockIdx.x * 16;
#pragma unroll
        for (int i = 0; i < 16; i++) {
            float2 v = ((const float2*)x)[(size_t)(t0 + i) * 256 + tid];
            xsall[i][2 * tid] = v.x; xsall[i][2 * tid + 1] = v.y;
        }
    }
    __syncthreads();

    for (int tt = 0; tt < 16; tt++) {
        int t = blockIdx.x * 16 + tt;

        float xv0 = xsall[tt][2 * tid], xv1 = xsall[tt][2 * tid + 1];
        float s = xv0 + xv1;
#pragma unroll
        for (int o = 16; o; o >>= 1) s += __shfl_xor_sync(0xffffffffu, s, o);
        if (lane == 0) wsum[wid] = s;
        __syncthreads();                                       // S1
        float sall = ((wsum[0] + wsum[1]) + (wsum[2] + wsum[3]))
                   + ((wsum[4] + wsum[5]) + (wsum[6] + wsum[7]));
        int keep = (sall / 512.0f) > 0.1f;
        float denom = sall + 1e-8f;
        float xn0 = keep ? xv0 / denom : 0.0f;
        float xn1 = keep ? xv1 / denom : 0.0f;
        if (keep)
            ((float2*)g_xn)[(size_t)t * 256 + tid] = make_float2(xn0, xn1);
        xsall[tt][2 * tid] = xn0; xsall[tt][2 * tid + 1] = xn1;
        __syncthreads();                                       // S2

        // logits: expert e = tid>>4, d-group g = tid&15
        float p = 0.0f;
#pragma unroll
        for (int i = 0; i < 32; i++)
            p += xsall[tt][g + 16 * i] * gwr[i];
        p += __shfl_down_sync(0xffffffffu, p, 8, 16);
        p += __shfl_down_sync(0xffffffffu, p, 4, 16);
        p += __shfl_down_sync(0xffffffffu, p, 2, 16);
        p += __shfl_down_sync(0xffffffffu, p, 1, 16);
        if (g == 0)
            ls[e] = p + gbe + jax_noise((uint32_t)(t * 16 + e));
        __syncthreads();                                       // S3

        // parallel top-2 + softmax on lanes 0..15
        if (tid < 16) {
            float l = ls[tid];
            float m1 = l; int am = tid;
#pragma unroll
            for (int o = 8; o; o >>= 1) {
                float om = __shfl_xor_sync(0xffffu, m1, o, 16);
                int   oa = __shfl_xor_sync(0xffffu, am, o, 16);
                if (om > m1 || (om == m1 && oa < am)) { m1 = om; am = oa; }
            }
            float lx = (tid == am) ? -3.4e38f : l;
            float m2 = lx; int am2 = tid;
#pragma unroll
            for (int o = 8; o; o >>= 1) {
                float om = __shfl_xor_sync(0xffffu, m2, o, 16);
                int   oa = __shfl_xor_sync(0xffffu, am2, o, 16);
                if (om > m2 || (om == m2 && oa < am2)) { m2 = om; am2 = oa; }
            }
            float pe = (l >= m2) ? expf(l - m1) : 0.0f;
            float sum = pe;
#pragma unroll
            for (int o = 8; o; o >>= 1) sum += __shfl_xor_sync(0xffffu, sum, o, 16);
            float pn = pe / sum;
            us[tid] += pn;
            float p0 = __shfl_sync(0xffffu, pn, am, 16);
            float p1 = __shfl_sync(0xffffu, pn, am2, 16);
            if (tid == 0) {
                sh_i0 = am; sh_i1 = am2; sh_p0 = p0; sh_p1 = p1;
                g_keep[t] = keep;
                g_topi[2*t] = am; g_topi[2*t+1] = am2;
                g_topp[2*t] = p0; g_topp[2*t+1] = p1;
                if (keep) {
                    int ia = atomicAdd(&g_nact, 1);
                    g_act[ia] = t;
                    int a0 = atomicAdd(&g_cnt[am], 1);
                    g_tok[am*CAP+a0] = t;  g_pair[am*CAP+a0] = 2*t;
                    int a1 = atomicAdd(&g_cnt[am2], 1);
                    g_tok[am2*CAP+a1] = t; g_pair[am2*CAP+a1] = 2*t+1;
                }
                if (out_size >= T * DDIM + 2 * T) {
                    out[T * DDIM + 2*t]     = (float)am;
                    out[T * DDIM + 2*t + 1] = (float)am2;
                }
            }
        }
        __syncthreads();                                       // S4

        if (!keep) {
            // inactive token: final = p0*z[i0] + p1*z[i1]
            float2 a = ((const float2*)g_z)[sh_i0 * 256 + tid];
            float2 b = ((const float2*)g_z)[sh_i1 * 256 + tid];
            float p0 = sh_p0, p1 = sh_p1;
            ((float2*)out)[(size_t)t * 256 + tid] =
                make_float2(p0*a.x + p1*b.x, p0*a.y + p1*b.y);
        } else {
            // zero the two staging rows for this token's assignments
            float4 z4 = make_float4(0.f, 0.f, 0.f, 0.f);
            float4* h4 = (float4*)(g_hbuf + (size_t)(2*t) * HDIM);     // 512 f4
#pragma unroll
            for (int i = 0; i < 2; i++) h4[tid + 256 * i] = z4;
            float4* c4 = (float4*)(g_contrib + (size_t)(2*t) * DDIM);  // 256 f4
            c4[tid] = z4;
        }
    }
    __syncthreads();
    if (tid < NEXP) atomicAdd(&g_usage[tid], us[tid]);
}

// ---------------- kernel 3: h partials = xn @ w1 (float2 weight stream) ---
// grid (16, HDIM/256=4, DDIM/128=4), 256 thr: col2=(tid&127)*2 (2 h-cols),
// half=tid>>7 (two 64-wide d sub-ranges). 16-token tiles, acc float2[16].
__global__ __launch_bounds__(256) void k_gemm1(const float* __restrict__ w1) {
    int e = blockIdx.x;
    int n = g_cnt[e];
    if (n == 0) return;
    int hc0 = blockIdx.y * 256;
    int d0  = blockIdx.z * 128;
    int col2 = (threadIdx.x & 127) * 2, half = threadIdx.x >> 7;

    __shared__ float xs[16][128];
    __shared__ int toks[16], pairs[16];

    for (int base = 0; base < n; base += 16) {
        int m = min(16, n - base);
        if (threadIdx.x < m) {
            toks[threadIdx.x]  = g_tok [e*CAP + base + threadIdx.x];
            pairs[threadIdx.x] = g_pair[e*CAP + base + threadIdx.x];
        }
        __syncthreads();
        for (int idx = threadIdx.x; idx < m * 32; idx += 256) {
            int r = idx >> 5, cc = idx & 31;
            ((float4*)xs[r])[cc] =
                ((const float4*)(g_xn + (size_t)toks[r] * DDIM + d0))[cc];
        }
        __syncthreads();

        const float* wp = w1 + ((size_t)e * DDIM + d0 + half * 64) * HDIM + hc0 + col2;
        float2 acc[16];
#pragma unroll
        for (int j = 0; j < 16; j++) acc[j] = make_float2(0.f, 0.f);
#pragma unroll 4
        for (int dd = 0; dd < 64; dd++) {
            float2 wv = *(const float2*)(wp + (size_t)dd * HDIM);
#pragma unroll
            for (int j = 0; j < 16; j++) {
                float xv = xs[j][half * 64 + dd];
                acc[j].x = fmaf(xv, wv.x, acc[j].x);
                acc[j].y = fmaf(xv, wv.y, acc[j].y);
            }
        }
        for (int j = 0; j < m; j++) {
            float* dst = &g_hbuf[(size_t)pairs[j] * HDIM + hc0 + col2];
            atomicAdd(dst,     acc[j].x);
            atomicAdd(dst + 1, acc[j].y);
        }
        __syncthreads();
    }
}

// ---------------- kernel 4: contrib partials = silu(h) @ w2 ---------------
// grid (16, DDIM/256=2, HDIM/128=8), 256 thr: col2=(tid&127)*2 (2 d-cols),
// half=tid>>7 (two 64-wide k sub-ranges). silu applied at tile load.
__global__ __launch_bounds__(256) void k_gemm2(const float* __restrict__ w2) {
    int e = blockIdx.x;
    int n = g_cnt[e];
    if (n == 0) return;
    int dc0 = blockIdx.y * 256;
    int k0  = blockIdx.z * 128;
    int col2 = (threadIdx.x & 127) * 2, half = threadIdx.x >> 7;

    __shared__ float hs[16][128];
    __shared__ int pairs[16];

    for (int base = 0; base < n; base += 16) {
        int m = min(16, n - base);
        if (threadIdx.x < m)
            pairs[threadIdx.x] = g_pair[e*CAP + base + threadIdx.x];
        __syncthreads();
        for (int idx = threadIdx.x; idx < m * 32; idx += 256) {
            int r = idx >> 5, cc = idx & 31;
            float4 v = ((const float4*)(g_hbuf + (size_t)pairs[r] * HDIM + k0))[cc];
            v.x = v.x / (1.0f + expf(-v.x));
            v.y = v.y / (1.0f + expf(-v.y));
            v.z = v.z / (1.0f + expf(-v.z));
            v.w = v.w / (1.0f + expf(-v.w));
            ((float4*)hs[r])[cc] = v;
        }
        __syncthreads();

        const float* wp = w2 + ((size_t)e * HDIM + k0 + half * 64) * DDIM + dc0 + col2;
        float2 acc[16];
#pragma unroll
        for (int j = 0; j < 16; j++) acc[j] = make_float2(0.f, 0.f);
#pragma unroll 4
        for (int kk = 0; kk < 64; kk++) {
            float2 wv = *(const float2*)(wp + (size_t)kk * DDIM);
#pragma unroll
            for (int j = 0; j < 16; j++) {
                float hv = hs[j][half * 64 + kk];
                acc[j].x = fmaf(hv, wv.x, acc[j].x);
                acc[j].y = fmaf(hv, wv.y, acc[j].y);
            }
        }
        for (int j = 0; j < m; j++) {
            float* dst = &g_contrib[(size_t)pairs[j] * DDIM + dc0 + col2];
            atomicAdd(dst,     acc[j].x);
            atomicAdd(dst + 1, acc[j].y);
        }
        __syncthreads();
    }
}

// ---------------- kernel 5: combine active rows (compacted) ---------------
__global__ void k_combine(const float* __restrict__ b2, float* __restrict__ out) {
    int c = threadIdx.x;               // 128 float4 per row
    int na = g_nact;
    for (int i = blockIdx.x; i < na; i += gridDim.x) {
        int t = g_act[i];
        int i0 = g_topi[2*t], i1 = g_topi[2*t+1];
        float p0 = g_topp[2*t], p1 = g_topp[2*t+1];
        float4 a = ((const float4*)(g_contrib + (size_t)(2*t)   * DDIM))[c];
        float4 b = ((const float4*)(g_contrib + (size_t)(2*t+1) * DDIM))[c];
        float4 ba = ((const float4*)(b2 + (size_t)i0 * DDIM))[c];
        float4 bb = ((const float4*)(b2 + (size_t)i1 * DDIM))[c];
        ((float4*)out)[(size_t)t * 128 + c] = make_float4(
            p0*(a.x+ba.x) + p1*(b.x+bb.x),
            p0*(a.y+ba.y) + p1*(b.y+bb.y),
            p0*(a.z+ba.z) + p1*(b.z+bb.z),
            p0*(a.w+ba.w) + p1*(b.w+bb.w));
    }
}

// ---------------- kernel 6: aux from usage --------------------------------
__global__ void k_aux(float* __restrict__ out, int out_size, int T) {
    if (threadIdx.x != 0) return;
    float usage[16]; float tot = 0.0f;
    for (int e = 0; e < 16; e++) { usage[e] = g_usage[e]; tot += usage[e]; }
    float imp[16]; float mean = 0.0f;
    for (int e = 0; e < 16; e++) { imp[e] = usage[e] / (tot + 1e-10f); mean += imp[e]; }
    mean /= 16.0f;
    float var = 0.0f;
    for (int e = 0; e < 16; e++) { float d = imp[e] - mean; var += d * d; }
    var /= 16.0f;
    float aux = sqrtf(var) / (mean + 1e-10f);
    if (out_size >= T * DDIM + 2 * T + 1)
        out[T * DDIM + 2 * T] = aux;
}

// ---------------- host launcher -------------------------------------------
extern "C" void kernel_launch(void* const* d_in, const int* in_sizes, int n_in,
                              void* d_out, int out_size) {
    const float* x  = (const float*)d_in[0];
    const float* gw = (const float*)d_in[1];
    const float* gb = (const float*)d_in[2];
    const float* w1 = (const float*)d_in[3];
    const float* b1 = (const float*)d_in[4];
    const float* w2 = (const float*)d_in[5];
    const float* b2 = (const float*)d_in[6];
    float* out = (float*)d_out;
    int T = in_sizes[0] / DDIM;        // 8192

    k_setup  <<<1, 256>>>(b1);
    k_z      <<<dim3(NEXP, 4), 128>>>(b1, w2, b2);
    k_gate   <<<T / 16, 256>>>(x, gw, gb, out, out_size, T);
    k_gemm1  <<<dim3(NEXP, 4, 4), 256>>>(w1);
    k_gemm2  <<<dim3(NEXP, 2, 8), 256>>>(w2);
    k_combine<<<256, 128>>>(b2, out);
    k_aux    <<<1, 32>>>(out, out_size, T);
}

// round 10
// speedup vs baseline: 4.5185x; 1.0185x over previous
#include <cuda_runtime.h>
#include <cstdint>

// Problem constants
#define NTOK   8192      // B*S = 4*2048
#define DDIM   512
#define NEXP   16
#define HDIM   1024
#define CAP    8192

// ---------------- scratch (device globals: allocation-free) ----------------
__device__ float g_xn[NTOK * DDIM];             // normalized x (active rows only)
__device__ float g_hbuf[(2 * NTOK) * HDIM];     // raw h partial sums (pre-silu)
__device__ float g_contrib[(2 * NTOK) * DDIM];  // raw h@w2 partial sums
__device__ int   g_tok [NEXP * CAP];
__device__ int   g_pair[NEXP * CAP];            // 2t+k
__device__ int   g_keep[NTOK];
__device__ int   g_topi[2 * NTOK];
__device__ float g_topp[2 * NTOK];
__device__ int   g_act[NTOK];                   // compacted active-token list
__device__ float g_z[NEXP * DDIM];              // expert output for zero input
__device__ float g_usage[NEXP];
__device__ int   g_cnt[NEXP];
__device__ int   g_nact;
__device__ int   g_bflag;

// ---------------- JAX threefry2x32, partitionable path (validated R5) -----
__device__ __forceinline__ uint32_t rotl32(uint32_t x, int r) {
    return (x << r) | (x >> (32 - r));
}

__device__ __forceinline__ void threefry2x32(uint32_t k0, uint32_t k1,
                                             uint32_t& x0, uint32_t& x1) {
    uint32_t k2 = k0 ^ k1 ^ 0x1BD11BDAu;
#define TF_RND(r) { x0 += x1; x1 = rotl32(x1, r); x1 ^= x0; }
    x0 += k0; x1 += k1;
    TF_RND(13) TF_RND(15) TF_RND(26) TF_RND(6)
    x0 += k1; x1 += k2 + 1u;
    TF_RND(17) TF_RND(29) TF_RND(16) TF_RND(24)
    x0 += k2; x1 += k0 + 2u;
    TF_RND(13) TF_RND(15) TF_RND(26) TF_RND(6)
    x0 += k0; x1 += k1 + 3u;
    TF_RND(17) TF_RND(29) TF_RND(16) TF_RND(24)
    x0 += k1; x1 += k2 + 4u;
    TF_RND(13) TF_RND(15) TF_RND(26) TF_RND(6)
    x0 += k2; x1 += k0 + 5u;
#undef TF_RND
}

__device__ __forceinline__ float jax_noise(uint32_t j) {
    uint32_t x0 = 0u, x1 = j;
    threefry2x32(0u, 42u, x0, x1);
    uint32_t bits = x0 ^ x1;
    uint32_t fb = (bits >> 9) | 0x3F800000u;
    float u01 = __uint_as_float(fb) - 1.0f;
    const float minval = __uint_as_float(0xBF7FFFFFu);
    float u = fmaf(u01, 2.0f, minval);
    u = fmaxf(minval, u);
    float w = -log1pf(-u * u);
    float p;
    if (w < 5.0f) {
        w -= 2.5f;
        p = 2.81022636e-08f;
        p = fmaf(p, w, 3.43273939e-07f);
        p = fmaf(p, w, -3.5233877e-06f);
        p = fmaf(p, w, -4.39150654e-06f);
        p = fmaf(p, w, 0.00021858087f);
        p = fmaf(p, w, -0.00125372503f);
        p = fmaf(p, w, -0.00417768164f);
        p = fmaf(p, w, 0.246640727f);
        p = fmaf(p, w, 1.50140941f);
    } else {
        w = sqrtf(w) - 3.0f;
        p = -0.000200214257f;
        p = fmaf(p, w, 0.000100950558f);
        p = fmaf(p, w, 0.00134934322f);
        p = fmaf(p, w, -0.00367342844f);
        p = fmaf(p, w, 0.00573950773f);
        p = fmaf(p, w, -0.0076224613f);
        p = fmaf(p, w, 0.00943887047f);
        p = fmaf(p, w, 1.00167406f);
        p = fmaf(p, w, 2.83297682f);
    }
    float nrm = 1.41421356f * (p * u);
    return nrm * 0.01f;
}

// ---------------- kernel 0: reset counters --------------------------------
__global__ void k_setup(const float* __restrict__ b1) {
    int tid = threadIdx.x;
    if (tid < NEXP) { g_cnt[tid] = 0; g_usage[tid] = 0.0f; }
    if (tid == 0) { g_bflag = 0; g_nact = 0; }
    __syncthreads();
    int nz = 0;
    for (int i = tid; i < NEXP * HDIM; i += blockDim.x)
        nz |= (b1[i] != 0.0f);
    if (__syncthreads_or(nz)) { if (tid == 0) g_bflag = 1; }
}

// ---------------- kernel 1: expert output for zero input ------------------
__global__ void k_z(const float* __restrict__ b1, const float* __restrict__ w2,
                    const float* __restrict__ b2) {
    int e = blockIdx.x;
    int d = blockIdx.y * 128 + threadIdx.x;
    if (g_bflag == 0) {               // b1 == 0 -> silu(0)=0 -> z = b2
        g_z[e * DDIM + d] = b2[e * DDIM + d];
        return;
    }
    __shared__ float s1[HDIM];
    for (int i = threadIdx.x; i < HDIM; i += 128) {
        float v = b1[e * HDIM + i];
        s1[i] = v / (1.0f + expf(-v));
    }
    __syncthreads();
    float acc = 0.0f;
    for (int h = 0; h < HDIM; h++)
        acc += s1[h] * w2[((size_t)e * HDIM + h) * DDIM + d];
    g_z[e * DDIM + d] = acc + b2[e * DDIM + d];
}

// ---------------- kernel 2: gate — smem-prefetched 16 tokens/block --------
__global__ __launch_bounds__(256) void k_gate(
    const float* __restrict__ x, const float* __restrict__ gw,
    const float* __restrict__ gb, float* __restrict__ out,
    int out_size, int T)
{
    __shared__ float xsall[16][DDIM];     // 32 KB
    __shared__ float wsum[8];
    __shared__ float ls[NEXP];
    __shared__ float us[NEXP];
    __shared__ float sh_p0, sh_p1;
    __shared__ int   sh_i0, sh_i1;

    int tid = threadIdx.x, lane = tid & 31, wid = tid >> 5;
    int e = tid >> 4, g = tid & 15;

    float gwr[32];
#pragma unroll
    for (int i = 0; i < 32; i++)
        gwr[i] = gw[(g + 16 * i) * NEXP + e];

    float gbe = (tid < NEXP) ? gb[tid] : 0.0f;
    if (tid < NEXP) us[tid] = 0.0f;

    {
        int t0 = blockIdx.x * 16;
#pragma unroll
        for (int i = 0; i < 16; i++) {
            float2 v = ((const float2*)x)[(size_t)(t0 + i) * 256 + tid];
            xsall[i][2 * tid] = v.x; xsall[i][2 * tid + 1] = v.y;
        }
    }
    __syncthreads();

    for (int tt = 0; tt < 16; tt++) {
        int t = blockIdx.x * 16 + tt;

        float xv0 = xsall[tt][2 * tid], xv1 = xsall[tt][2 * tid + 1];
        float s = xv0 + xv1;
#pragma unroll
        for (int o = 16; o; o >>= 1) s += __shfl_xor_sync(0xffffffffu, s, o);
        if (lane == 0) wsum[wid] = s;
        __syncthreads();                                       // S1
        float sall = ((wsum[0] + wsum[1]) + (wsum[2] + wsum[3]))
                   + ((wsum[4] + wsum[5]) + (wsum[6] + wsum[7]));
        int keep = (sall / 512.0f) > 0.1f;
        float denom = sall + 1e-8f;
        float xn0 = keep ? xv0 / denom : 0.0f;
        float xn1 = keep ? xv1 / denom : 0.0f;
        if (keep)
            ((float2*)g_xn)[(size_t)t * 256 + tid] = make_float2(xn0, xn1);
        xsall[tt][2 * tid] = xn0; xsall[tt][2 * tid + 1] = xn1;
        __syncthreads();                                       // S2

        float p = 0.0f;
#pragma unroll
        for (int i = 0; i < 32; i++)
            p += xsall[tt][g + 16 * i] * gwr[i];
        p += __shfl_down_sync(0xffffffffu, p, 8, 16);
        p += __shfl_down_sync(0xffffffffu, p, 4, 16);
        p += __shfl_down_sync(0xffffffffu, p, 2, 16);
        p += __shfl_down_sync(0xffffffffu, p, 1, 16);
        if (g == 0)
            ls[e] = p + gbe + jax_noise((uint32_t)(t * 16 + e));
        __syncthreads();                                       // S3

        if (tid < 16) {
            float l = ls[tid];
            float m1 = l; int am = tid;
#pragma unroll
            for (int o = 8; o; o >>= 1) {
                float om = __shfl_xor_sync(0xffffu, m1, o, 16);
                int   oa = __shfl_xor_sync(0xffffu, am, o, 16);
                if (om > m1 || (om == m1 && oa < am)) { m1 = om; am = oa; }
            }
            float lx = (tid == am) ? -3.4e38f : l;
            float m2 = lx; int am2 = tid;
#pragma unroll
            for (int o = 8; o; o >>= 1) {
                float om = __shfl_xor_sync(0xffffu, m2, o, 16);
                int   oa = __shfl_xor_sync(0xffffu, am2, o, 16);
                if (om > m2 || (om == m2 && oa < am2)) { m2 = om; am2 = oa; }
            }
            float pe = (l >= m2) ? expf(l - m1) : 0.0f;
            float sum = pe;
#pragma unroll
            for (int o = 8; o; o >>= 1) sum += __shfl_xor_sync(0xffffu, sum, o, 16);
            float pn = pe / sum;
            us[tid] += pn;
            float p0 = __shfl_sync(0xffffu, pn, am, 16);
            float p1 = __shfl_sync(0xffffu, pn, am2, 16);
            if (tid == 0) {
                sh_i0 = am; sh_i1 = am2; sh_p0 = p0; sh_p1 = p1;
                g_keep[t] = keep;
                g_topi[2*t] = am; g_topi[2*t+1] = am2;
                g_topp[2*t] = p0; g_topp[2*t+1] = p1;
                if (keep) {
                    int ia = atomicAdd(&g_nact, 1);
                    g_act[ia] = t;
                    int a0 = atomicAdd(&g_cnt[am], 1);
                    g_tok[am*CAP+a0] = t;  g_pair[am*CAP+a0] = 2*t;
                    int a1 = atomicAdd(&g_cnt[am2], 1);
                    g_tok[am2*CAP+a1] = t; g_pair[am2*CAP+a1] = 2*t+1;
                }
                if (out_size >= T * DDIM + 2 * T) {
                    out[T * DDIM + 2*t]     = (float)am;
                    out[T * DDIM + 2*t + 1] = (float)am2;
                }
            }
        }
        __syncthreads();                                       // S4

        if (!keep) {
            float2 a = ((const float2*)g_z)[sh_i0 * 256 + tid];
            float2 b = ((const float2*)g_z)[sh_i1 * 256 + tid];
            float p0 = sh_p0, p1 = sh_p1;
            ((float2*)out)[(size_t)t * 256 + tid] =
                make_float2(p0*a.x + p1*b.x, p0*a.y + p1*b.y);
        } else {
            float4 z4 = make_float4(0.f, 0.f, 0.f, 0.f);
            float4* h4 = (float4*)(g_hbuf + (size_t)(2*t) * HDIM);     // 512 f4
#pragma unroll
            for (int i = 0; i < 2; i++) h4[tid + 256 * i] = z4;
            float4* c4 = (float4*)(g_contrib + (size_t)(2*t) * DDIM);  // 256 f4
            c4[tid] = z4;
        }
    }
    __syncthreads();
    if (tid < NEXP) atomicAdd(&g_usage[tid], us[tid]);
}

// ---------------- kernel 3: h partials = xn @ w1 --------------------------
// grid (16, HDIM/256=4, DDIM/64=8) = 512 blocks, 256 thr.
// col2=(tid&127)*2 (2 h-cols of a 256-col stripe), half=tid>>7 (32-wide d).
__global__ __launch_bounds__(256) void k_gemm1(const float* __restrict__ w1) {
    int e = blockIdx.x;
    int n = g_cnt[e];
    if (n == 0) return;
    int hc0 = blockIdx.y * 256;
    int d0  = blockIdx.z * 64;
    int col2 = (threadIdx.x & 127) * 2, half = threadIdx.x >> 7;

    __shared__ float xs[16][64];
    __shared__ int pairs[16];

    for (int base = 0; base < n; base += 16) {
        int m = min(16, n - base);
        if (threadIdx.x < m)
            pairs[threadIdx.x] = g_pair[e*CAP + base + threadIdx.x];
        if (threadIdx.x < 16 * 16) {   // 16 rows x 16 float4 = one pass
            int r = threadIdx.x >> 4, cc = threadIdx.x & 15;
            int tok = g_tok[e*CAP + base + r];
            if (r < m)
                ((float4*)xs[r])[cc] =
                    ((const float4*)(g_xn + (size_t)tok * DDIM + d0))[cc];
        }
        __syncthreads();

        const float* wp = w1 + ((size_t)e * DDIM + d0 + half * 32) * HDIM + hc0 + col2;
        float2 acc[16];
#pragma unroll
        for (int j = 0; j < 16; j++) acc[j] = make_float2(0.f, 0.f);
#pragma unroll 4
        for (int dd = 0; dd < 32; dd++) {
            float2 wv = *(const float2*)(wp + (size_t)dd * HDIM);
#pragma unroll
            for (int j = 0; j < 16; j++) {
                float xv = xs[j][half * 32 + dd];
                acc[j].x = fmaf(xv, wv.x, acc[j].x);
                acc[j].y = fmaf(xv, wv.y, acc[j].y);
            }
        }
        for (int j = 0; j < m; j++) {
            float* dst = &g_hbuf[(size_t)pairs[j] * HDIM + hc0 + col2];
            atomicAdd(dst,     acc[j].x);
            atomicAdd(dst + 1, acc[j].y);
        }
        __syncthreads();
    }
}

// ---------------- kernel 4: contrib partials = silu(h) @ w2 ---------------
// grid (16, DDIM/256=2, HDIM/64=16) = 512 blocks, 256 thr.
// col2=(tid&127)*2 (2 d-cols of a 256-col stripe), half=tid>>7 (32-wide k).
__global__ __launch_bounds__(256) void k_gemm2(const float* __restrict__ w2) {
    int e = blockIdx.x;
    int n = g_cnt[e];
    if (n == 0) return;
    int dc0 = blockIdx.y * 256;
    int k0  = blockIdx.z * 64;
    int col2 = (threadIdx.x & 127) * 2, half = threadIdx.x >> 7;

    __shared__ float hs[16][64];
    __shared__ int pairs[16];

    for (int base = 0; base < n; base += 16) {
        int m = min(16, n - base);
        if (threadIdx.x < m)
            pairs[threadIdx.x] = g_pair[e*CAP + base + threadIdx.x];
        __syncthreads();
        if (threadIdx.x < 16 * 16) {   // 16 rows x 16 float4 = one pass
            int r = threadIdx.x >> 4, cc = threadIdx.x & 15;
            if (r < m) {
                float4 v = ((const float4*)(g_hbuf + (size_t)pairs[r] * HDIM + k0))[cc];
                v.x = v.x / (1.0f + expf(-v.x));
                v.y = v.y / (1.0f + expf(-v.y));
                v.z = v.z / (1.0f + expf(-v.z));
                v.w = v.w / (1.0f + expf(-v.w));
                ((float4*)hs[r])[cc] = v;
            }
        }
        __syncthreads();

        const float* wp = w2 + ((size_t)e * HDIM + k0 + half * 32) * DDIM + dc0 + col2;
        float2 acc[16];
#pragma unroll
        for (int j = 0; j < 16; j++) acc[j] = make_float2(0.f, 0.f);
#pragma unroll 4
        for (int kk = 0; kk < 32; kk++) {
            float2 wv = *(const float2*)(wp + (size_t)kk * DDIM);
#pragma unroll
            for (int j = 0; j < 16; j++) {
                float hv = hs[j][half * 32 + kk];
                acc[j].x = fmaf(hv, wv.x, acc[j].x);
                acc[j].y = fmaf(hv, wv.y, acc[j].y);
            }
        }
        for (int j = 0; j < m; j++) {
            float* dst = &g_contrib[(size_t)pairs[j] * DDIM + dc0 + col2];
            atomicAdd(dst,     acc[j].x);
            atomicAdd(dst + 1, acc[j].y);
        }
        __syncthreads();
    }
}

// ---------------- kernel 5: combine active rows (compacted) ---------------
__global__ void k_combine(const float* __restrict__ b2, float* __restrict__ out) {
    int c = threadIdx.x;               // 128 float4 per row
    int na = g_nact;
    for (int i = blockIdx.x; i < na; i += gridDim.x) {
        int t = g_act[i];
        int i0 = g_topi[2*t], i1 = g_topi[2*t+1];
        float p0 = g_topp[2*t], p1 = g_topp[2*t+1];
        float4 a = ((const float4*)(g_contrib + (size_t)(2*t)   * DDIM))[c];
        float4 b = ((const float4*)(g_contrib + (size_t)(2*t+1) * DDIM))[c];
        float4 ba = ((const float4*)(b2 + (size_t)i0 * DDIM))[c];
        float4 bb = ((const float4*)(b2 + (size_t)i1 * DDIM))[c];
        ((float4*)out)[(size_t)t * 128 + c] = make_float4(
            p0*(a.x+ba.x) + p1*(b.x+bb.x),
            p0*(a.y+ba.y) + p1*(b.y+bb.y),
            p0*(a.z+ba.z) + p1*(b.z+bb.z),
            p0*(a.w+ba.w) + p1*(b.w+bb.w));
    }
}

// ---------------- kernel 6: aux from usage --------------------------------
__global__ void k_aux(float* __restrict__ out, int out_size, int T) {
    if (threadIdx.x != 0) return;
    float usage[16]; float tot = 0.0f;
    for (int e = 0; e < 16; e++) { usage[e] = g_usage[e]; tot += usage[e]; }
    float imp[16]; float mean = 0.0f;
    for (int e = 0; e < 16; e++) { imp[e] = usage[e] / (tot + 1e-10f); mean += imp[e]; }
    mean /= 16.0f;
    float var = 0.0f;
    for (int e = 0; e < 16; e++) { float d = imp[e] - mean; var += d * d; }
    var /= 16.0f;
    float aux = sqrtf(var) / (mean + 1e-10f);
    if (out_size >= T * DDIM + 2 * T + 1)
        out[T * DDIM + 2 * T] = aux;
}

// ---------------- host launcher -------------------------------------------
extern "C" void kernel_launch(void* const* d_in, const int* in_sizes, int n_in,
                              void* d_out, int out_size) {
    const float* x  = (const float*)d_in[0];
    const float* gw = (const float*)d_in[1];
    const float* gb = (const float*)d_in[2];
    const float* w1 = (const float*)d_in[3];
    const float* b1 = (const float*)d_in[4];
    const float* w2 = (const float*)d_in[5];
    const float* b2 = (const float*)d_in[6];
    float* out = (float*)d_out;
    int T = in_sizes[0] / DDIM;        // 8192

    k_setup  <<<1, 256>>>(b1);
    k_z      <<<dim3(NEXP, 4), 128>>>(b1, w2, b2);
    k_gate   <<<T / 16, 256>>>(x, gw, gb, out, out_size, T);
    k_gemm1  <<<dim3(NEXP, 4, 8), 256>>>(w1);
    k_gemm2  <<<dim3(NEXP, 2, 16), 256>>>(w2);
    k_combine<<<256, 128>>>(b2, out);
    k_aux    <<<1, 32>>>(out, out_size, T);
}

// round 11
// speedup vs baseline: 4.8800x; 1.0800x over previous
#include <cuda_runtime.h>
#include <cstdint>

// Problem constants
#define NTOK   8192      // B*S = 4*2048
#define DDIM   512
#define NEXP   16
#define HDIM   1024
#define CAP    8192

// ---------------- scratch (device globals: allocation-free) ----------------
__device__ float g_xn[NTOK * DDIM];             // normalized x (active rows only)
__device__ float g_hbuf[(2 * NTOK) * HDIM];     // raw h partial sums (pre-silu)
__device__ float g_contrib[(2 * NTOK) * DDIM];  // raw h@w2 partial sums
__device__ int   g_tok [NEXP * CAP];
__device__ int   g_pair[NEXP * CAP];            // 2t+k
__device__ int   g_keep[NTOK];
__device__ int   g_topi[2 * NTOK];
__device__ float g_topp[2 * NTOK];
__device__ int   g_act[NTOK];                   // compacted active-token list
__device__ float g_z[NEXP * DDIM];              // expert output for zero input
__device__ float g_usage[NEXP];
__device__ int   g_cnt[NEXP];
__device__ int   g_nact;
__device__ int   g_bflag;

// ---------------- JAX threefry2x32, partitionable path (validated R5) -----
__device__ __forceinline__ uint32_t rotl32(uint32_t x, int r) {
    return (x << r) | (x >> (32 - r));
}

__device__ __forceinline__ void threefry2x32(uint32_t k0, uint32_t k1,
                                             uint32_t& x0, uint32_t& x1) {
    uint32_t k2 = k0 ^ k1 ^ 0x1BD11BDAu;
#define TF_RND(r) { x0 += x1; x1 = rotl32(x1, r); x1 ^= x0; }
    x0 += k0; x1 += k1;
    TF_RND(13) TF_RND(15) TF_RND(26) TF_RND(6)
    x0 += k1; x1 += k2 + 1u;
    TF_RND(17) TF_RND(29) TF_RND(16) TF_RND(24)
    x0 += k2; x1 += k0 + 2u;
    TF_RND(13) TF_RND(15) TF_RND(26) TF_RND(6)
    x0 += k0; x1 += k1 + 3u;
    TF_RND(17) TF_RND(29) TF_RND(16) TF_RND(24)
    x0 += k1; x1 += k2 + 4u;
    TF_RND(13) TF_RND(15) TF_RND(26) TF_RND(6)
    x0 += k2; x1 += k0 + 5u;
#undef TF_RND
}

__device__ __forceinline__ float jax_noise(uint32_t j) {
    uint32_t x0 = 0u, x1 = j;
    threefry2x32(0u, 42u, x0, x1);
    uint32_t bits = x0 ^ x1;
    uint32_t fb = (bits >> 9) | 0x3F800000u;
    float u01 = __uint_as_float(fb) - 1.0f;
    const float minval = __uint_as_float(0xBF7FFFFFu);
    float u = fmaf(u01, 2.0f, minval);
    u = fmaxf(minval, u);
    float w = -log1pf(-u * u);
    float p;
    if (w < 5.0f) {
        w -= 2.5f;
        p = 2.81022636e-08f;
        p = fmaf(p, w, 3.43273939e-07f);
        p = fmaf(p, w, -3.5233877e-06f);
        p = fmaf(p, w, -4.39150654e-06f);
        p = fmaf(p, w, 0.00021858087f);
        p = fmaf(p, w, -0.00125372503f);
        p = fmaf(p, w, -0.00417768164f);
        p = fmaf(p, w, 0.246640727f);
        p = fmaf(p, w, 1.50140941f);
    } else {
        w = sqrtf(w) - 3.0f;
        p = -0.000200214257f;
        p = fmaf(p, w, 0.000100950558f);
        p = fmaf(p, w, 0.00134934322f);
        p = fmaf(p, w, -0.00367342844f);
        p = fmaf(p, w, 0.00573950773f);
        p = fmaf(p, w, -0.0076224613f);
        p = fmaf(p, w, 0.00943887047f);
        p = fmaf(p, w, 1.00167406f);
        p = fmaf(p, w, 2.83297682f);
    }
    float nrm = 1.41421356f * (p * u);
    return nrm * 0.01f;
}

// ---------------- kernel 0: reset counters --------------------------------
__global__ void k_setup(const float* __restrict__ b1) {
    int tid = threadIdx.x;
    if (tid < NEXP) { g_cnt[tid] = 0; g_usage[tid] = 0.0f; }
    if (tid == 0) { g_bflag = 0; g_nact = 0; }
    __syncthreads();
    int nz = 0;
    for (int i = tid; i < NEXP * HDIM; i += blockDim.x)
        nz |= (b1[i] != 0.0f);
    if (__syncthreads_or(nz)) { if (tid == 0) g_bflag = 1; }
}

// ---------------- kernel 1: expert output for zero input ------------------
__global__ void k_z(const float* __restrict__ b1, const float* __restrict__ w2,
                    const float* __restrict__ b2) {
    int e = blockIdx.x;
    int d = blockIdx.y * 128 + threadIdx.x;
    if (g_bflag == 0) {               // b1 == 0 -> silu(0)=0 -> z = b2
        g_z[e * DDIM + d] = b2[e * DDIM + d];
        return;
    }
    __shared__ float s1[HDIM];
    for (int i = threadIdx.x; i < HDIM; i += 128) {
        float v = b1[e * HDIM + i];
        s1[i] = v / (1.0f + expf(-v));
    }
    __syncthreads();
    float acc = 0.0f;
    for (int h = 0; h < HDIM; h++)
        acc += s1[h] * w2[((size_t)e * HDIM + h) * DDIM + d];
    g_z[e * DDIM + d] = acc + b2[e * DDIM + d];
}

// ---------------- kernel 2: gate — smem-prefetched 16 tokens/block --------
__global__ __launch_bounds__(256) void k_gate(
    const float* __restrict__ x, const float* __restrict__ gw,
    const float* __restrict__ gb, float* __restrict__ out,
    int out_size, int T)
{
    __shared__ float xsall[16][DDIM];     // 32 KB
    __shared__ float wsum[8];
    __shared__ float ls[NEXP];
    __shared__ float us[NEXP];
    __shared__ float sh_p0, sh_p1;
    __shared__ int   sh_i0, sh_i1;

    int tid = threadIdx.x, lane = tid & 31, wid = tid >> 5;
    int e = tid >> 4, g = tid & 15;

    float gwr[32];
#pragma unroll
    for (int i = 0; i < 32; i++)
        gwr[i] = gw[(g + 16 * i) * NEXP + e];

    float gbe = (tid < NEXP) ? gb[tid] : 0.0f;
    if (tid < NEXP) us[tid] = 0.0f;

    {
        int t0 = blockIdx.x * 16;
#pragma unroll
        for (int i = 0; i < 16; i++) {
            float2 v = ((const float2*)x)[(size_t)(t0 + i) * 256 + tid];
            xsall[i][2 * tid] = v.x; xsall[i][2 * tid + 1] = v.y;
        }
    }
    __syncthreads();

    for (int tt = 0; tt < 16; tt++) {
        int t = blockIdx.x * 16 + tt;

        float xv0 = xsall[tt][2 * tid], xv1 = xsall[tt][2 * tid + 1];
        float s = xv0 + xv1;
#pragma unroll
        for (int o = 16; o; o >>= 1) s += __shfl_xor_sync(0xffffffffu, s, o);
        if (lane == 0) wsum[wid] = s;
        __syncthreads();                                       // S1
        float sall = ((wsum[0] + wsum[1]) + (wsum[2] + wsum[3]))
                   + ((wsum[4] + wsum[5]) + (wsum[6] + wsum[7]));
        int keep = (sall / 512.0f) > 0.1f;
        float denom = sall + 1e-8f;
        float xn0 = keep ? xv0 / denom : 0.0f;
        float xn1 = keep ? xv1 / denom : 0.0f;
        if (keep)
            ((float2*)g_xn)[(size_t)t * 256 + tid] = make_float2(xn0, xn1);
        xsall[tt][2 * tid] = xn0; xsall[tt][2 * tid + 1] = xn1;
        __syncthreads();                                       // S2

        float p = 0.0f;
#pragma unroll
        for (int i = 0; i < 32; i++)
            p += xsall[tt][g + 16 * i] * gwr[i];
        p += __shfl_down_sync(0xffffffffu, p, 8, 16);
        p += __shfl_down_sync(0xffffffffu, p, 4, 16);
        p += __shfl_down_sync(0xffffffffu, p, 2, 16);
        p += __shfl_down_sync(0xffffffffu, p, 1, 16);
        if (g == 0)
            ls[e] = p + gbe + jax_noise((uint32_t)(t * 16 + e));
        __syncthreads();                                       // S3

        if (tid < 16) {
            float l = ls[tid];
            float m1 = l; int am = tid;
#pragma unroll
            for (int o = 8; o; o >>= 1) {
                float om = __shfl_xor_sync(0xffffu, m1, o, 16);
                int   oa = __shfl_xor_sync(0xffffu, am, o, 16);
                if (om > m1 || (om == m1 && oa < am)) { m1 = om; am = oa; }
            }
            float lx = (tid == am) ? -3.4e38f : l;
            float m2 = lx; int am2 = tid;
#pragma unroll
            for (int o = 8; o; o >>= 1) {
                float om = __shfl_xor_sync(0xffffu, m2, o, 16);
                int   oa = __shfl_xor_sync(0xffffu, am2, o, 16);
                if (om > m2 || (om == m2 && oa < am2)) { m2 = om; am2 = oa; }
            }
            float pe = (l >= m2) ? expf(l - m1) : 0.0f;
            float sum = pe;
#pragma unroll
            for (int o = 8; o; o >>= 1) sum += __shfl_xor_sync(0xffffu, sum, o, 16);
            float pn = pe / sum;
            us[tid] += pn;
            float p0 = __shfl_sync(0xffffu, pn, am, 16);
            float p1 = __shfl_sync(0xffffu, pn, am2, 16);
            if (tid == 0) {
                sh_i0 = am; sh_i1 = am2; sh_p0 = p0; sh_p1 = p1;
                g_keep[t] = keep;
                g_topi[2*t] = am; g_topi[2*t+1] = am2;
                g_topp[2*t] = p0; g_topp[2*t+1] = p1;
                if (keep) {
                    int ia = atomicAdd(&g_nact, 1);
                    g_act[ia] = t;
                    int a0 = atomicAdd(&g_cnt[am], 1);
                    g_tok[am*CAP+a0] = t;  g_pair[am*CAP+a0] = 2*t;
                    int a1 = atomicAdd(&g_cnt[am2], 1);
                    g_tok[am2*CAP+a1] = t; g_pair[am2*CAP+a1] = 2*t+1;
                }
                if (out_size >= T * DDIM + 2 * T) {
                    out[T * DDIM + 2*t]     = (float)am;
                    out[T * DDIM + 2*t + 1] = (float)am2;
                }
            }
        }
        __syncthreads();                                       // S4

        if (!keep) {
            float2 a = ((const float2*)g_z)[sh_i0 * 256 + tid];
            float2 b = ((const float2*)g_z)[sh_i1 * 256 + tid];
            float p0 = sh_p0, p1 = sh_p1;
            ((float2*)out)[(size_t)t * 256 + tid] =
                make_float2(p0*a.x + p1*b.x, p0*a.y + p1*b.y);
        } else {
            float4 z4 = make_float4(0.f, 0.f, 0.f, 0.f);
            float4* h4 = (float4*)(g_hbuf + (size_t)(2*t) * HDIM);     // 512 f4
#pragma unroll
            for (int i = 0; i < 2; i++) h4[tid + 256 * i] = z4;
            float4* c4 = (float4*)(g_contrib + (size_t)(2*t) * DDIM);  // 256 f4
            c4[tid] = z4;
        }
    }
    __syncthreads();
    if (tid < NEXP) atomicAdd(&g_usage[tid], us[tid]);
}

// ---------------- kernel 3: h partials = xn @ w1 --------------------------
// grid (16, HDIM/256=4, DDIM/64=8) = 512 blocks, 256 thr.
// Inner loop batches 8 independent float2 weight loads (MLP=8) before FMAs.
__global__ __launch_bounds__(256) void k_gemm1(const float* __restrict__ w1) {
    int e = blockIdx.x;
    int n = g_cnt[e];
    if (n == 0) return;
    int hc0 = blockIdx.y * 256;
    int d0  = blockIdx.z * 64;
    int col2 = (threadIdx.x & 127) * 2, half = threadIdx.x >> 7;

    __shared__ float xs[16][64];
    __shared__ int pairs[16];

    for (int base = 0; base < n; base += 16) {
        int m = min(16, n - base);
        if (threadIdx.x < m)
            pairs[threadIdx.x] = g_pair[e*CAP + base + threadIdx.x];
        if (threadIdx.x < 16 * 16) {   // 16 rows x 16 float4 = one pass
            int r = threadIdx.x >> 4, cc = threadIdx.x & 15;
            int tok = g_tok[e*CAP + base + r];
            if (r < m)
                ((float4*)xs[r])[cc] =
                    ((const float4*)(g_xn + (size_t)tok * DDIM + d0))[cc];
        }
        __syncthreads();

        const float* wp = w1 + ((size_t)e * DDIM + d0 + half * 32) * HDIM + hc0 + col2;
        float2 acc[16];
#pragma unroll
        for (int j = 0; j < 16; j++) acc[j] = make_float2(0.f, 0.f);
#pragma unroll
        for (int c8 = 0; c8 < 32; c8 += 8) {
            float2 wbuf[8];
#pragma unroll
            for (int u = 0; u < 8; u++)
                wbuf[u] = *(const float2*)(wp + (size_t)(c8 + u) * HDIM);
#pragma unroll
            for (int u = 0; u < 8; u++) {
#pragma unroll
                for (int j = 0; j < 16; j++) {
                    float xv = xs[j][half * 32 + c8 + u];
                    acc[j].x = fmaf(xv, wbuf[u].x, acc[j].x);
                    acc[j].y = fmaf(xv, wbuf[u].y, acc[j].y);
                }
            }
        }
        for (int j = 0; j < m; j++) {
            float* dst = &g_hbuf[(size_t)pairs[j] * HDIM + hc0 + col2];
            atomicAdd(dst,     acc[j].x);
            atomicAdd(dst + 1, acc[j].y);
        }
        __syncthreads();
    }
}

// ---------------- kernel 4: contrib partials = silu(h) @ w2 ---------------
// grid (16, DDIM/256=2, HDIM/64=16) = 512 blocks, 256 thr.
// Same 8-deep weight load batching.
__global__ __launch_bounds__(256) void k_gemm2(const float* __restrict__ w2) {
    int e = blockIdx.x;
    int n = g_cnt[e];
    if (n == 0) return;
    int dc0 = blockIdx.y * 256;
    int k0  = blockIdx.z * 64;
    int col2 = (threadIdx.x & 127) * 2, half = threadIdx.x >> 7;

    __shared__ float hs[16][64];
    __shared__ int pairs[16];

    for (int base = 0; base < n; base += 16) {
        int m = min(16, n - base);
        if (threadIdx.x < m)
            pairs[threadIdx.x] = g_pair[e*CAP + base + threadIdx.x];
        __syncthreads();
        if (threadIdx.x < 16 * 16) {   // 16 rows x 16 float4 = one pass
            int r = threadIdx.x >> 4, cc = threadIdx.x & 15;
            if (r < m) {
                float4 v = ((const float4*)(g_hbuf + (size_t)pairs[r] * HDIM + k0))[cc];
                v.x = v.x / (1.0f + expf(-v.x));
                v.y = v.y / (1.0f + expf(-v.y));
                v.z = v.z / (1.0f + expf(-v.z));
                v.w = v.w / (1.0f + expf(-v.w));
                ((float4*)hs[r])[cc] = v;
            }
        }
        __syncthreads();

        const float* wp = w2 + ((size_t)e * HDIM + k0 + half * 32) * DDIM + dc0 + col2;
        float2 acc[16];
#pragma unroll
        for (int j = 0; j < 16; j++) acc[j] = make_float2(0.f, 0.f);
#pragma unroll
        for (int c8 = 0; c8 < 32; c8 += 8) {
            float2 wbuf[8];
#pragma unroll
            for (int u = 0; u < 8; u++)
                wbuf[u] = *(const float2*)(wp + (size_t)(c8 + u) * DDIM);
#pragma unroll
            for (int u = 0; u < 8; u++) {
#pragma unroll
                for (int j = 0; j < 16; j++) {
                    float hv = hs[j][half * 32 + c8 + u];
                    acc[j].x = fmaf(hv, wbuf[u].x, acc[j].x);
                    acc[j].y = fmaf(hv, wbuf[u].y, acc[j].y);
                }
            }
        }
        for (int j = 0; j < m; j++) {
            float* dst = &g_contrib[(size_t)pairs[j] * DDIM + dc0 + col2];
            atomicAdd(dst,     acc[j].x);
            atomicAdd(dst + 1, acc[j].y);
        }
        __syncthreads();
    }
}

// ---------------- kernel 5: combine active rows (compacted) ---------------
__global__ void k_combine(const float* __restrict__ b2, float* __restrict__ out) {
    int c = threadIdx.x;               // 128 float4 per row
    int na = g_nact;
    for (int i = blockIdx.x; i < na; i += gridDim.x) {
        int t = g_act[i];
        int i0 = g_topi[2*t], i1 = g_topi[2*t+1];
        float p0 = g_topp[2*t], p1 = g_topp[2*t+1];
        float4 a = ((const float4*)(g_contrib + (size_t)(2*t)   * DDIM))[c];
        float4 b = ((const float4*)(g_contrib + (size_t)(2*t+1) * DDIM))[c];
        float4 ba = ((const float4*)(b2 + (size_t)i0 * DDIM))[c];
        float4 bb = ((const float4*)(b2 + (size_t)i1 * DDIM))[c];
        ((float4*)out)[(size_t)t * 128 + c] = make_float4(
            p0*(a.x+ba.x) + p1*(b.x+bb.x),
            p0*(a.y+ba.y) + p1*(b.y+bb.y),
            p0*(a.z+ba.z) + p1*(b.z+bb.z),
            p0*(a.w+ba.w) + p1*(b.w+bb.w));
    }
}

// ---------------- kernel 6: aux from usage --------------------------------
__global__ void k_aux(float* __restrict__ out, int out_size, int T) {
    if (threadIdx.x != 0) return;
    float usage[16]; float tot = 0.0f;
    for (int e = 0; e < 16; e++) { usage[e] = g_usage[e]; tot += usage[e]; }
    float imp[16]; float mean = 0.0f;
    for (int e = 0; e < 16; e++) { imp[e] = usage[e] / (tot + 1e-10f); mean += imp[e]; }
    mean /= 16.0f;
    float var = 0.0f;
    for (int e = 0; e < 16; e++) { float d = imp[e] - mean; var += d * d; }
    var /= 16.0f;
    float aux = sqrtf(var) / (mean + 1e-10f);
    if (out_size >= T * DDIM + 2 * T + 1)
        out[T * DDIM + 2 * T] = aux;
}

// ---------------- host launcher -------------------------------------------
extern "C" void kernel_launch(void* const* d_in, const int* in_sizes, int n_in,
                              void* d_out, int out_size) {
    const float* x  = (const float*)d_in[0];
    const float* gw = (const float*)d_in[1];
    const float* gb = (const float*)d_in[2];
    const float* w1 = (const float*)d_in[3];
    const float* b1 = (const float*)d_in[4];
    const float* w2 = (const float*)d_in[5];
    const float* b2 = (const float*)d_in[6];
    float* out = (float*)d_out;
    int T = in_sizes[0] / DDIM;        // 8192

    k_setup  <<<1, 256>>>(b1);
    k_z      <<<dim3(NEXP, 4), 128>>>(b1, w2, b2);
    k_gate   <<<T / 16, 256>>>(x, gw, gb, out, out_size, T);
    k_gemm1  <<<dim3(NEXP, 4, 8), 256>>>(w1);
    k_gemm2  <<<dim3(NEXP, 2, 16), 256>>>(w2);
    k_combine<<<256, 128>>>(b2, out);
    k_aux    <<<1, 32>>>(out, out_size, T);
}